// round 9
// baseline (speedup 1.0000x reference)
#include <cuda_runtime.h>
#include <cuda_fp16.h>
#include <math.h>
#include <stdint.h>

#define DM    1024
#define DFF   4096
#define SQ    2048
#define BATCH 2
#define ROWS  (BATCH*SQ)   /* 4096 */
#define DK    64
#define NH    16
#define DM3   (3*DM)

// ---------------- scratch (device globals; no allocation) ----------------
__device__ __half g_xn_h [ROWS*DM];
__device__ __half g_qkv_h[ROWS*DM3];
__device__ __half g_ctx_h[ROWS*DM];
__device__ float  g_x1   [ROWS*DM];
__device__ __half g_h_h  [ROWS*DFF];
__device__ __half g_wqkvh[DM*DM3];
__device__ float  g_bqkv [DM3];
__device__ __half g_wrh  [DM*DM + DM*DFF + DFF*DM];   // half wo|w1|w2

// ---------------- helpers -------------------------------------------------
__device__ __forceinline__ void mma16(float* c,
    uint32_t a0, uint32_t a1, uint32_t a2, uint32_t a3,
    uint32_t b0, uint32_t b1)
{
    asm volatile(
      "mma.sync.aligned.m16n8k16.row.col.f32.f16.f16.f32 "
      "{%0,%1,%2,%3},{%4,%5,%6,%7},{%8,%9},{%0,%1,%2,%3};"
      : "+f"(c[0]), "+f"(c[1]), "+f"(c[2]), "+f"(c[3])
      : "r"(a0), "r"(a1), "r"(a2), "r"(a3), "r"(b0), "r"(b1));
}
__device__ __forceinline__ void ldsm_x4(uint32_t& r0, uint32_t& r1,
                                        uint32_t& r2, uint32_t& r3, uint32_t addr)
{
    asm volatile("ldmatrix.sync.aligned.m8n8.x4.shared.b16 {%0,%1,%2,%3}, [%4];"
                 : "=r"(r0), "=r"(r1), "=r"(r2), "=r"(r3) : "r"(addr));
}
__device__ __forceinline__ void ldsm_x4_t(uint32_t& r0, uint32_t& r1,
                                          uint32_t& r2, uint32_t& r3, uint32_t addr)
{
    asm volatile("ldmatrix.sync.aligned.m8n8.x4.trans.shared.b16 {%0,%1,%2,%3}, [%4];"
                 : "=r"(r0), "=r"(r1), "=r"(r2), "=r"(r3) : "r"(addr));
}
__device__ __forceinline__ uint32_t s2u(const void* p) {
    uint32_t a;
    asm("{.reg .u64 t; cvta.to.shared.u64 t, %1; cvt.u32.u64 %0, t;}"
        : "=r"(a) : "l"(p));
    return a;
}
__device__ __forceinline__ void cpasync16(uint32_t dst, const void* src) {
    asm volatile("cp.async.cg.shared.global [%0], [%1], 16;" :: "r"(dst), "l"(src));
}
__device__ __forceinline__ uint32_t packh2(float a, float b) {
    __half2 h = __floats2half2_rn(a, b);
    return *(uint32_t*)&h;
}
#define CP_COMMIT() asm volatile("cp.async.commit_group;")
#define CP_WAIT1()  asm volatile("cp.async.wait_group 1;")

// ---------------- half-convert: wo|w1|w2 -> half --------------------------
#define NW4_WO (DM*DM/4)
#define NW4_W1 (DM*DFF/4)
#define NW4_W2 (DFF*DM/4)
__global__ void __launch_bounds__(256) half_all(
    const float* __restrict__ wo, const float* __restrict__ w1,
    const float* __restrict__ w2, __half* __restrict__ dst)
{
    int i = blockIdx.x * 256 + threadIdx.x;
    const float* src;
    int local;
    if (i < NW4_WO)                        { src = wo; local = i; }
    else if (i < NW4_WO + NW4_W1)          { src = w1; local = i - NW4_WO; }
    else if (i < NW4_WO + NW4_W1 + NW4_W2) { src = w2; local = i - NW4_WO - NW4_W1; }
    else return;
    float4 v = *(const float4*)(src + (size_t)local*4);
    *(uint2*)(dst + (size_t)i*4) = make_uint2(packh2(v.x, v.y), packh2(v.z, v.w));
}

// ---------------- pack wq|wk|wv -> half [1024][3072], biases f32 ----------
__global__ void __launch_bounds__(256) pack_qkv(
    const float* __restrict__ wq, const float* __restrict__ wk,
    const float* __restrict__ wv, const float* __restrict__ bq,
    const float* __restrict__ bk, const float* __restrict__ bv,
    __half* __restrict__ W, float* __restrict__ B)
{
    const int NW = 3 * (DM*DM/4);
    int idx = blockIdx.x * 256 + threadIdx.x;
    if (idx < NW) {
        int m  = idx / (DM*DM/4);
        int r  = idx - m * (DM*DM/4);
        int k  = r >> 8;
        int j4 = r & 255;
        const float* src = (m == 0) ? wq : (m == 1) ? wk : wv;
        float4 v = *(const float4*)(src + k*DM + j4*4);
        *(uint2*)(W + (size_t)k*DM3 + m*DM + j4*4) =
            make_uint2(packh2(v.x, v.y), packh2(v.z, v.w));
    } else if (idx < NW + 3*256) {
        int i = idx - NW;
        int m = i >> 8, j4 = i & 255;
        const float* src = (m == 0) ? bq : (m == 1) ? bk : bv;
        *(float4*)(B + m*DM + j4*4) = *(const float4*)(src + j4*4);
    }
}

// ---------------- LayerNorm (half output) ---------------------------------
__global__ void __launch_bounds__(256) ln_kernel(
    const float* __restrict__ X, const float* __restrict__ gamma,
    const float* __restrict__ beta, __half* __restrict__ Y)
{
    const int row = blockIdx.x, tid = threadIdx.x;
    const float* xr = X + (size_t)row * DM;
    float4 xv = *(const float4*)(xr + tid*4);
    float s  = xv.x + xv.y + xv.z + xv.w;
    float s2 = xv.x*xv.x + xv.y*xv.y + xv.z*xv.z + xv.w*xv.w;
    #pragma unroll
    for (int o = 16; o; o >>= 1) {
        s  += __shfl_xor_sync(0xffffffffu, s,  o);
        s2 += __shfl_xor_sync(0xffffffffu, s2, o);
    }
    __shared__ float sm1[8], sm2[8];
    if ((tid & 31) == 0) { sm1[tid>>5] = s; sm2[tid>>5] = s2; }
    __syncthreads();
    float ts = 0.f, ts2 = 0.f;
    #pragma unroll
    for (int i = 0; i < 8; i++) { ts += sm1[i]; ts2 += sm2[i]; }
    float mean = ts * (1.0f / DM);
    float var  = (ts2 - ts * mean) * (1.0f / (DM - 1));   // unbiased (ddof=1)
    float inv  = 1.0f / (sqrtf(var) + 1e-6f);             // eps OUTSIDE sqrt
    float4 g4 = *(const float4*)(gamma + tid*4);
    float4 b4 = *(const float4*)(beta  + tid*4);
    *(uint2*)(Y + (size_t)row * DM + tid*4) = make_uint2(
        packh2(g4.x * (xv.x - mean) * inv + b4.x,
               g4.y * (xv.y - mean) * inv + b4.y),
        packh2(g4.z * (xv.z - mean) * inv + b4.z,
               g4.w * (xv.w - mean) * inv + b4.w));
}

// ---------------- fp16 GEMM 128x128x64, 8 warps, 64x32 warp tile ----------
// C = A@B + bias ; EPI: 0=half out (qkv), 1=relu half out, 2=+residual f32
// 256 thr = 8 warps (2m x 4n). acc 64 regs -> ~130 regs/thr, 2 CTAs/SM,
// 16 warps/SM (4/SMSP) for latency hiding.
#define BK 64
#define AS 72     /* halves; 144B row stride */
#define BS 136    /* halves; 272B row stride */
#define A_HALVES (128*AS)
#define B_HALVES (BK*BS)
#define GEMM_SMEM (2*(A_HALVES + B_HALVES)*2)

template<int EPI>
__global__ void __launch_bounds__(256, 2) gemm_tc(
    const __half* __restrict__ A, const __half* __restrict__ Bm,
    const float* __restrict__ bias, const float* __restrict__ res,
    void* __restrict__ Cv, int M, int N, int K)
{
    extern __shared__ __half hsm[];
    __half* As = hsm;
    __half* Bs = hsm + 2*A_HALVES;

    const int tid  = threadIdx.x;
    const int lane = tid & 31, wid = tid >> 5;
    const int wm = wid >> 2, wn = wid & 3;     // 2 x 4
    const int gid = lane >> 2, tig = lane & 3;
    const int bm = blockIdx.y * 128, bn = blockIdx.x * 128;

    // prefetch geometry (256 threads, 16B chunks)
    const int ar0 = tid >> 3, ac = (tid & 7) * 8;     // A rows 0..31, 4 x 32
    const int br0 = tid >> 4, bc = (tid & 15) * 8;    // B rows 0..15, 4 x 16
    const uint32_t as_u = s2u(As);
    const uint32_t bs_u = s2u(Bs);

    const int NT = K >> 6;

    auto prefetch = [&](int kt, int buf) {
        const __half* Ag = A + (size_t)(bm + ar0) * K + kt*BK + ac;
        uint32_t ad = as_u + (uint32_t)(buf*A_HALVES + ar0*AS + ac) * 2;
        #pragma unroll
        for (int i = 0; i < 4; i++)
            cpasync16(ad + (uint32_t)(i*32*AS*2), Ag + (size_t)(i*32)*K);
        const __half* Bg = Bm + (size_t)(kt*BK + br0) * N + bn + bc;
        uint32_t bd = bs_u + (uint32_t)(buf*B_HALVES + br0*BS + bc) * 2;
        #pragma unroll
        for (int i = 0; i < 4; i++)
            cpasync16(bd + (uint32_t)(i*16*BS*2), Bg + (size_t)(i*16)*N);
    };

    // ldsm lane addressing
    const int a_row_l = (lane & 7) + (lane & 8);
    const int a_kcol  = ((lane >> 4) & 1) * 8;
    const uint32_t a_lane_off = (uint32_t)(((wm*64 + a_row_l) * AS + a_kcol) * 2);
    const int b_row_l = lane & 15;
    const int b_ncol  = ((lane >> 4) & 1) * 8;
    const uint32_t b_lane_off = (uint32_t)((b_row_l * BS + wn*32 + b_ncol) * 2);

    float acc[4][4][4];
    #pragma unroll
    for (int a = 0; a < 4; a++)
        #pragma unroll
        for (int b = 0; b < 4; b++)
            #pragma unroll
            for (int c = 0; c < 4; c++) acc[a][b][c] = 0.f;

    prefetch(0, 0); CP_COMMIT();
    if (NT > 1) prefetch(1, 1);
    CP_COMMIT();

    for (int kt = 0; kt < NT; kt++) {
        CP_WAIT1();
        __syncthreads();
        const uint32_t abase = as_u + (uint32_t)((kt & 1) * A_HALVES * 2) + a_lane_off;
        const uint32_t bbase = bs_u + (uint32_t)((kt & 1) * B_HALVES * 2) + b_lane_off;
        #pragma unroll
        for (int ks = 0; ks < 4; ks++) {
            uint32_t af[4][4];
            #pragma unroll
            for (int mt = 0; mt < 4; mt++)
                ldsm_x4(af[mt][0], af[mt][1], af[mt][2], af[mt][3],
                        abase + (uint32_t)(mt*16*AS*2 + ks*32));
            #pragma unroll
            for (int p = 0; p < 2; p++) {
                uint32_t b0, b1, b2, b3;
                ldsm_x4_t(b0, b1, b2, b3,
                          bbase + (uint32_t)(ks*16*BS*2 + p*32));
                #pragma unroll
                for (int mt = 0; mt < 4; mt++) {
                    mma16(acc[mt][2*p],   af[mt][0], af[mt][1], af[mt][2], af[mt][3], b0, b1);
                    mma16(acc[mt][2*p+1], af[mt][0], af[mt][1], af[mt][2], af[mt][3], b2, b3);
                }
            }
        }
        __syncthreads();
        if (kt + 2 < NT) prefetch(kt + 2, kt & 1);
        CP_COMMIT();
    }

    #pragma unroll
    for (int mt = 0; mt < 4; mt++) {
        const int r0 = bm + wm*64 + mt*16 + gid;
        #pragma unroll
        for (int nt = 0; nt < 4; nt++) {
            const int cn = bn + wn*32 + nt*8 + tig*2;
            float bx = bias[cn], by = bias[cn+1];
            float2 v0 = make_float2(acc[mt][nt][0] + bx, acc[mt][nt][1] + by);
            float2 v1 = make_float2(acc[mt][nt][2] + bx, acc[mt][nt][3] + by);
            size_t o0 = (size_t)r0 * N + cn;
            size_t o1 = o0 + (size_t)8 * N;
            if (EPI == 0) {        // half out (qkv)
                __half* C = (__half*)Cv;
                *(uint32_t*)(C + o0) = packh2(v0.x, v0.y);
                *(uint32_t*)(C + o1) = packh2(v1.x, v1.y);
            }
            if (EPI == 1) {        // relu -> half out
                __half* C = (__half*)Cv;
                *(uint32_t*)(C + o0) = packh2(fmaxf(v0.x, 0.f), fmaxf(v0.y, 0.f));
                *(uint32_t*)(C + o1) = packh2(fmaxf(v1.x, 0.f), fmaxf(v1.y, 0.f));
            }
            if (EPI == 2) {        // +residual, f32 out
                float* C = (float*)Cv;
                float2 r0v = *(const float2*)(res + o0);
                float2 r1v = *(const float2*)(res + o1);
                *(float2*)(C + o0) = make_float2(v0.x + r0v.x, v0.y + r0v.y);
                *(float2*)(C + o1) = make_float2(v1.x + r1v.x, v1.y + r1v.y);
            }
        }
    }
}

// ---------------- fp16 flash attention, register-resident P ---------------
#define QS 72
#define AQ_H (64*QS)
#define ATT_SMEM ((AQ_H + 2*AQ_H + 2*AQ_H) * 2 + 2*64*4)

__global__ void __launch_bounds__(128) attn_tc(
    const __half* __restrict__ QKV, const int* __restrict__ mask,
    __half* __restrict__ O)
{
    extern __shared__ __half hsm[];
    __half* q_s = hsm;
    __half* k_s = q_s + AQ_H;          // 2 stages
    __half* v_s = k_s + 2*AQ_H;        // 2 stages
    int*    m_s = (int*)(v_s + 2*AQ_H);// [2][64]

    const int tid = threadIdx.x, lane = tid & 31, w = tid >> 5;
    const int gid = lane >> 2, tig = lane & 3;
    const int qt = blockIdx.x, h = blockIdx.y, b = blockIdx.z;
    const __half* Qp = QKV + (size_t)b * SQ * DM3 + (size_t)h * DK;
    const __half* Kp = Qp + DM;
    const __half* Vp = Qp + 2*DM;
    const uint32_t qs_u = s2u(q_s);
    const uint32_t ks_u = s2u(k_s);
    const uint32_t vs_u = s2u(v_s);

    auto kv_prefetch = [&](int t, int buf) {
        #pragma unroll
        for (int i = 0; i < 4; i++) {
            int c = tid + i*128;
            int r = c >> 3, c8 = c & 7;
            size_t goff = (size_t)(t*64 + r) * DM3 + c8*8;
            uint32_t soff = (uint32_t)((buf*AQ_H + r*QS + c8*8) * 2);
            cpasync16(ks_u + soff, Kp + goff);
            cpasync16(vs_u + soff, Vp + goff);
        }
    };

    kv_prefetch(0, 0); CP_COMMIT();

    for (int i = tid; i < 64*8; i += 128) {
        int r = i >> 3, c8 = i & 7;
        *(uint4*)&q_s[r*QS + c8*8] =
            *(const uint4*)(Qp + (size_t)(qt*64 + r) * DM3 + c8*8);
    }

    const int a_row_l = (lane & 7) + (lane & 8);
    const int a_kcol  = ((lane >> 4) & 1) * 8;
    const uint32_t q_lane = (uint32_t)(((w*16 + a_row_l) * QS + a_kcol) * 2);
    const int b_row_l = lane & 15;
    const int b_col_l = ((lane >> 4) & 1) * 8;

    float o[8][4];
    #pragma unroll
    for (int nt = 0; nt < 8; nt++)
        #pragma unroll
        for (int i = 0; i < 4; i++) o[nt][i] = 0.f;
    float l0 = 0.f, l1 = 0.f;
    const int NTI = SQ/64;

    for (int t = 0; t < NTI; t++) {
        if (t + 1 < NTI) kv_prefetch(t + 1, (t + 1) & 1);
        CP_COMMIT();
        if (tid < 64) m_s[(t & 1)*64 + tid] = mask[b*SQ + t*64 + tid];
        CP_WAIT1();
        __syncthreads();
        const uint32_t kbase = ks_u + (uint32_t)((t & 1) * AQ_H * 2);
        const uint32_t vbase = vs_u + (uint32_t)((t & 1) * AQ_H * 2);
        const int* mb = m_s + (t & 1) * 64;

        float s[8][4];
        #pragma unroll
        for (int nt = 0; nt < 8; nt++)
            #pragma unroll
            for (int i = 0; i < 4; i++) s[nt][i] = 0.f;
        #pragma unroll
        for (int ks = 0; ks < 4; ks++) {
            uint32_t a0, a1, a2, a3;
            ldsm_x4(a0, a1, a2, a3, qs_u + q_lane + (uint32_t)(ks*32));
            #pragma unroll
            for (int p = 0; p < 4; p++) {
                uint32_t r0, r1, r2, r3;
                ldsm_x4(r0, r1, r2, r3,
                    kbase + (uint32_t)(((p*16 + b_row_l)*QS + ks*16 + b_col_l) * 2));
                mma16(s[2*p],   a0, a1, a2, a3, r0, r2);
                mma16(s[2*p+1], a0, a1, a2, a3, r1, r3);
            }
        }

        uint32_t ph[8][2];
        #pragma unroll
        for (int nt = 0; nt < 8; nt++) {
            const int c0 = nt*8 + tig*2;
            const bool z0 = (mb[c0] == 0), z1 = (mb[c0+1] == 0);
            float p0 = __expf(z0 ? -1e9f : s[nt][0] * 0.125f);
            float p1 = __expf(z1 ? -1e9f : s[nt][1] * 0.125f);
            float p2 = __expf(z0 ? -1e9f : s[nt][2] * 0.125f);
            float p3 = __expf(z1 ? -1e9f : s[nt][3] * 0.125f);
            l0 += p0 + p1;  l1 += p2 + p3;
            ph[nt][0] = packh2(p0, p1);
            ph[nt][1] = packh2(p2, p3);
        }

        #pragma unroll
        for (int ks = 0; ks < 4; ks++) {
            uint32_t pa0 = ph[2*ks][0],   pa1 = ph[2*ks][1];
            uint32_t pa2 = ph[2*ks+1][0], pa3 = ph[2*ks+1][1];
            #pragma unroll
            for (int p = 0; p < 4; p++) {
                uint32_t r0, r1, r2, r3;
                ldsm_x4_t(r0, r1, r2, r3,
                    vbase + (uint32_t)(((ks*16 + b_row_l)*QS + p*16 + b_col_l) * 2));
                mma16(o[2*p],   pa0, pa1, pa2, pa3, r0, r1);
                mma16(o[2*p+1], pa0, pa1, pa2, pa3, r2, r3);
            }
        }
        __syncthreads();
    }

    l0 += __shfl_xor_sync(0xffffffffu, l0, 1);
    l0 += __shfl_xor_sync(0xffffffffu, l0, 2);
    l1 += __shfl_xor_sync(0xffffffffu, l1, 1);
    l1 += __shfl_xor_sync(0xffffffffu, l1, 2);
    const float n0 = 1.0f / l0, n1 = 1.0f / l1;
    #pragma unroll
    for (int nt = 0; nt < 8; nt++) {
        const int cn = h*DK + nt*8 + tig*2;
        size_t r0 = (size_t)(b*SQ + qt*64 + w*16 + gid) * DM + cn;
        size_t r1 = r0 + (size_t)8 * DM;
        *(uint32_t*)(O + r0) = packh2(o[nt][0]*n0, o[nt][1]*n0);
        *(uint32_t*)(O + r1) = packh2(o[nt][2]*n1, o[nt][3]*n1);
    }
}

// --------------------------------------------------------------------------
extern "C" void kernel_launch(void* const* d_in, const int* in_sizes, int n_in,
                              void* d_out, int out_size)
{
    const float* x    = (const float*)d_in[0];
    const int*   mask = (const int*)  d_in[1];
    const float* wq = (const float*)d_in[2],  *bq = (const float*)d_in[3];
    const float* wk = (const float*)d_in[4],  *bk = (const float*)d_in[5];
    const float* wv = (const float*)d_in[6],  *bv = (const float*)d_in[7];
    const float* wo = (const float*)d_in[8],  *bo = (const float*)d_in[9];
    const float* w1 = (const float*)d_in[10], *b1 = (const float*)d_in[11];
    const float* w2 = (const float*)d_in[12], *b2 = (const float*)d_in[13];
    const float* g1 = (const float*)d_in[14], *be1 = (const float*)d_in[15];
    const float* g2 = (const float*)d_in[16], *be2 = (const float*)d_in[17];
    float* out = (float*)d_out;

    __half *xn, *qkvh, *ctxh, *hbuf, *Wqh, *Wrh;
    float *x1, *Bq;
    cudaGetSymbolAddress((void**)&xn,   g_xn_h);
    cudaGetSymbolAddress((void**)&qkvh, g_qkv_h);
    cudaGetSymbolAddress((void**)&ctxh, g_ctx_h);
    cudaGetSymbolAddress((void**)&x1,   g_x1);
    cudaGetSymbolAddress((void**)&hbuf, g_h_h);
    cudaGetSymbolAddress((void**)&Wqh,  g_wqkvh);
    cudaGetSymbolAddress((void**)&Bq,   g_bqkv);
    cudaGetSymbolAddress((void**)&Wrh,  g_wrh);
    __half* wo_h = Wrh;
    __half* w1_h = Wrh + DM*DM;
    __half* w2_h = Wrh + DM*DM + DM*DFF;

    cudaFuncSetAttribute(gemm_tc<0>, cudaFuncAttributeMaxDynamicSharedMemorySize, GEMM_SMEM);
    cudaFuncSetAttribute(gemm_tc<1>, cudaFuncAttributeMaxDynamicSharedMemorySize, GEMM_SMEM);
    cudaFuncSetAttribute(gemm_tc<2>, cudaFuncAttributeMaxDynamicSharedMemorySize, GEMM_SMEM);
    cudaFuncSetAttribute(attn_tc,    cudaFuncAttributeMaxDynamicSharedMemorySize, ATT_SMEM);

    dim3 gQKV(DM3/128, ROWS/128);    // 24 x 32
    dim3 gProj(DM/128,  ROWS/128);   // 8 x 32
    dim3 gFF1 (DFF/128, ROWS/128);   // 32 x 32

    // 0) weight prep (half)
    pack_qkv<<<(3*(DM*DM/4) + 3*256 + 255)/256, 256>>>(wq, wk, wv, bq, bk, bv, Wqh, Bq);
    half_all<<<((NW4_WO + NW4_W1 + NW4_W2) + 255)/256, 256>>>(wo, w1, w2, Wrh);
    // 1) LN1 -> half
    ln_kernel<<<ROWS, 256>>>(x, g1, be1, xn);
    // 2) fused QKV projection (fp16 mma, half out)
    gemm_tc<0><<<gQKV, 256, GEMM_SMEM>>>(xn, Wqh, Bq, nullptr, qkvh, ROWS, DM3, DM);
    // 3) fused masked flash attention (fp16) -> ctx half
    attn_tc<<<dim3(SQ/64, NH, BATCH), 128, ATT_SMEM>>>(qkvh, mask, ctxh);
    // 4) out-proj + residual(x) -> x1 (f32)
    gemm_tc<2><<<gProj, 256, GEMM_SMEM>>>(ctxh, wo_h, bo, x, x1, ROWS, DM, DM);
    // 5) LN2 -> half
    ln_kernel<<<ROWS, 256>>>(x1, g2, be2, xn);
    // 6) FFN up + relu -> half
    gemm_tc<1><<<gFF1, 256, GEMM_SMEM>>>(xn, w1_h, b1, nullptr, hbuf, ROWS, DFF, DM);
    // 7) FFN down + residual(x1) -> out (f32)
    gemm_tc<2><<<gProj, 256, GEMM_SMEM>>>(hbuf, w2_h, b2, x1, out, ROWS, DM, DFF);
}

// round 11
// speedup vs baseline: 1.0044x; 1.0044x over previous
#include <cuda_runtime.h>
#include <cuda_fp16.h>
#include <math.h>
#include <stdint.h>

#define DM    1024
#define DFF   4096
#define SQ    2048
#define BATCH 2
#define ROWS  (BATCH*SQ)   /* 4096 */
#define DK    64
#define NH    16
#define DM3   (3*DM)

// ---------------- scratch (device globals; no allocation) ----------------
__device__ __half g_xn_h [ROWS*DM];
__device__ __half g_qkv_h[ROWS*DM3];
__device__ __half g_ctx_h[ROWS*DM];
__device__ float  g_x1   [ROWS*DM];
__device__ __half g_h_h  [ROWS*DFF];
__device__ __half g_wqkvh[DM*DM3];
__device__ float  g_bqkv [DM3];
__device__ __half g_wrh  [DM*DM + DM*DFF + DFF*DM];   // half wo|w1|w2

// ---------------- helpers -------------------------------------------------
__device__ __forceinline__ void mma16(float* c,
    uint32_t a0, uint32_t a1, uint32_t a2, uint32_t a3,
    uint32_t b0, uint32_t b1)
{
    asm volatile(
      "mma.sync.aligned.m16n8k16.row.col.f32.f16.f16.f32 "
      "{%0,%1,%2,%3},{%4,%5,%6,%7},{%8,%9},{%0,%1,%2,%3};"
      : "+f"(c[0]), "+f"(c[1]), "+f"(c[2]), "+f"(c[3])
      : "r"(a0), "r"(a1), "r"(a2), "r"(a3), "r"(b0), "r"(b1));
}
__device__ __forceinline__ void ldsm_x4(uint32_t& r0, uint32_t& r1,
                                        uint32_t& r2, uint32_t& r3, uint32_t addr)
{
    asm volatile("ldmatrix.sync.aligned.m8n8.x4.shared.b16 {%0,%1,%2,%3}, [%4];"
                 : "=r"(r0), "=r"(r1), "=r"(r2), "=r"(r3) : "r"(addr));
}
__device__ __forceinline__ void ldsm_x4_t(uint32_t& r0, uint32_t& r1,
                                          uint32_t& r2, uint32_t& r3, uint32_t addr)
{
    asm volatile("ldmatrix.sync.aligned.m8n8.x4.trans.shared.b16 {%0,%1,%2,%3}, [%4];"
                 : "=r"(r0), "=r"(r1), "=r"(r2), "=r"(r3) : "r"(addr));
}
__device__ __forceinline__ uint32_t s2u(const void* p) {
    uint32_t a;
    asm("{.reg .u64 t; cvta.to.shared.u64 t, %1; cvt.u32.u64 %0, t;}"
        : "=r"(a) : "l"(p));
    return a;
}
__device__ __forceinline__ void cpasync16(uint32_t dst, const void* src) {
    asm volatile("cp.async.cg.shared.global [%0], [%1], 16;" :: "r"(dst), "l"(src));
}
__device__ __forceinline__ uint32_t packh2(float a, float b) {
    __half2 h = __floats2half2_rn(a, b);
    return *(uint32_t*)&h;
}
#define CP_COMMIT() asm volatile("cp.async.commit_group;")
#define CP_WAIT1()  asm volatile("cp.async.wait_group 1;")

// ---------------- half-convert: wo|w1|w2 -> half --------------------------
#define NW4_WO (DM*DM/4)
#define NW4_W1 (DM*DFF/4)
#define NW4_W2 (DFF*DM/4)
__global__ void __launch_bounds__(256) half_all(
    const float* __restrict__ wo, const float* __restrict__ w1,
    const float* __restrict__ w2, __half* __restrict__ dst)
{
    int i = blockIdx.x * 256 + threadIdx.x;
    const float* src;
    int local;
    if (i < NW4_WO)                        { src = wo; local = i; }
    else if (i < NW4_WO + NW4_W1)          { src = w1; local = i - NW4_WO; }
    else if (i < NW4_WO + NW4_W1 + NW4_W2) { src = w2; local = i - NW4_WO - NW4_W1; }
    else return;
    float4 v = *(const float4*)(src + (size_t)local*4);
    *(uint2*)(dst + (size_t)i*4) = make_uint2(packh2(v.x, v.y), packh2(v.z, v.w));
}

// ---------------- pack wq|wk|wv -> half [1024][3072], biases f32 ----------
__global__ void __launch_bounds__(256) pack_qkv(
    const float* __restrict__ wq, const float* __restrict__ wk,
    const float* __restrict__ wv, const float* __restrict__ bq,
    const float* __restrict__ bk, const float* __restrict__ bv,
    __half* __restrict__ W, float* __restrict__ B)
{
    const int NW = 3 * (DM*DM/4);
    int idx = blockIdx.x * 256 + threadIdx.x;
    if (idx < NW) {
        int m  = idx / (DM*DM/4);
        int r  = idx - m * (DM*DM/4);
        int k  = r >> 8;
        int j4 = r & 255;
        const float* src = (m == 0) ? wq : (m == 1) ? wk : wv;
        float4 v = *(const float4*)(src + k*DM + j4*4);
        *(uint2*)(W + (size_t)k*DM3 + m*DM + j4*4) =
            make_uint2(packh2(v.x, v.y), packh2(v.z, v.w));
    } else if (idx < NW + 3*256) {
        int i = idx - NW;
        int m = i >> 8, j4 = i & 255;
        const float* src = (m == 0) ? bq : (m == 1) ? bk : bv;
        *(float4*)(B + m*DM + j4*4) = *(const float4*)(src + j4*4);
    }
}

// ---------------- LayerNorm (half output) ---------------------------------
__global__ void __launch_bounds__(256) ln_kernel(
    const float* __restrict__ X, const float* __restrict__ gamma,
    const float* __restrict__ beta, __half* __restrict__ Y)
{
    const int row = blockIdx.x, tid = threadIdx.x;
    const float* xr = X + (size_t)row * DM;
    float4 xv = *(const float4*)(xr + tid*4);
    float s  = xv.x + xv.y + xv.z + xv.w;
    float s2 = xv.x*xv.x + xv.y*xv.y + xv.z*xv.z + xv.w*xv.w;
    #pragma unroll
    for (int o = 16; o; o >>= 1) {
        s  += __shfl_xor_sync(0xffffffffu, s,  o);
        s2 += __shfl_xor_sync(0xffffffffu, s2, o);
    }
    __shared__ float sm1[8], sm2[8];
    if ((tid & 31) == 0) { sm1[tid>>5] = s; sm2[tid>>5] = s2; }
    __syncthreads();
    float ts = 0.f, ts2 = 0.f;
    #pragma unroll
    for (int i = 0; i < 8; i++) { ts += sm1[i]; ts2 += sm2[i]; }
    float mean = ts * (1.0f / DM);
    float var  = (ts2 - ts * mean) * (1.0f / (DM - 1));   // unbiased (ddof=1)
    float inv  = 1.0f / (sqrtf(var) + 1e-6f);             // eps OUTSIDE sqrt
    float4 g4 = *(const float4*)(gamma + tid*4);
    float4 b4 = *(const float4*)(beta  + tid*4);
    *(uint2*)(Y + (size_t)row * DM + tid*4) = make_uint2(
        packh2(g4.x * (xv.x - mean) * inv + b4.x,
               g4.y * (xv.y - mean) * inv + b4.y),
        packh2(g4.z * (xv.z - mean) * inv + b4.z,
               g4.w * (xv.w - mean) * inv + b4.w));
}

// ---------------- fp16 GEMM 128x128x64, ldmatrix, 4 warps 64x64 -----------
// (R8 config verbatim: measured best)
// C = A@B + bias ; EPI: 0=half out (qkv), 1=relu half out, 2=+residual f32
#define BK 64
#define AS 72
#define BS 136
#define A_HALVES (128*AS)
#define B_HALVES (BK*BS)
#define GEMM_SMEM (2*(A_HALVES + B_HALVES)*2)

template<int EPI>
__global__ void __launch_bounds__(128, 2) gemm_tc(
    const __half* __restrict__ A, const __half* __restrict__ Bm,
    const float* __restrict__ bias, const float* __restrict__ res,
    void* __restrict__ Cv, int M, int N, int K)
{
    extern __shared__ __half hsm[];
    __half* As = hsm;
    __half* Bs = hsm + 2*A_HALVES;

    const int tid  = threadIdx.x;
    const int lane = tid & 31, wid = tid >> 5;
    const int wm = wid >> 1, wn = wid & 1;
    const int gid = lane >> 2, tig = lane & 3;
    const int bm = blockIdx.y * 128, bn = blockIdx.x * 128;

    const int ar0 = tid >> 3, ac = (tid & 7) * 8;
    const int br0 = tid >> 4, bc = (tid & 15) * 8;
    const uint32_t as_u = s2u(As);
    const uint32_t bs_u = s2u(Bs);

    const int NT = K >> 6;

    auto prefetch = [&](int kt, int buf) {
        const __half* Ag = A + (size_t)(bm + ar0) * K + kt*BK + ac;
        uint32_t ad = as_u + (uint32_t)(buf*A_HALVES + ar0*AS + ac) * 2;
        #pragma unroll
        for (int i = 0; i < 8; i++)
            cpasync16(ad + (uint32_t)(i*16*AS*2), Ag + (size_t)(i*16)*K);
        const __half* Bg = Bm + (size_t)(kt*BK + br0) * N + bn + bc;
        uint32_t bd = bs_u + (uint32_t)(buf*B_HALVES + br0*BS + bc) * 2;
        #pragma unroll
        for (int i = 0; i < 8; i++)
            cpasync16(bd + (uint32_t)(i*8*BS*2), Bg + (size_t)(i*8)*N);
    };

    const int a_row_l = (lane & 7) + (lane & 8);
    const int a_kcol  = ((lane >> 4) & 1) * 8;
    const uint32_t a_lane_off = (uint32_t)(((wm*64 + a_row_l) * AS + a_kcol) * 2);
    const int b_row_l = lane & 15;
    const int b_ncol  = ((lane >> 4) & 1) * 8;
    const uint32_t b_lane_off = (uint32_t)((b_row_l * BS + wn*64 + b_ncol) * 2);

    float acc[4][8][4];
    #pragma unroll
    for (int a = 0; a < 4; a++)
        #pragma unroll
        for (int b = 0; b < 8; b++)
            #pragma unroll
            for (int c = 0; c < 4; c++) acc[a][b][c] = 0.f;

    prefetch(0, 0); CP_COMMIT();
    if (NT > 1) prefetch(1, 1);
    CP_COMMIT();

    for (int kt = 0; kt < NT; kt++) {
        CP_WAIT1();
        __syncthreads();
        const uint32_t abase = as_u + (uint32_t)((kt & 1) * A_HALVES * 2) + a_lane_off;
        const uint32_t bbase = bs_u + (uint32_t)((kt & 1) * B_HALVES * 2) + b_lane_off;
        #pragma unroll
        for (int ks = 0; ks < 4; ks++) {
            uint32_t af[4][4];
            #pragma unroll
            for (int mt = 0; mt < 4; mt++)
                ldsm_x4(af[mt][0], af[mt][1], af[mt][2], af[mt][3],
                        abase + (uint32_t)(mt*16*AS*2 + ks*32));
            #pragma unroll
            for (int p = 0; p < 4; p++) {
                uint32_t b0, b1, b2, b3;
                ldsm_x4_t(b0, b1, b2, b3,
                          bbase + (uint32_t)(ks*16*BS*2 + p*32));
                #pragma unroll
                for (int mt = 0; mt < 4; mt++) {
                    mma16(acc[mt][2*p],   af[mt][0], af[mt][1], af[mt][2], af[mt][3], b0, b1);
                    mma16(acc[mt][2*p+1], af[mt][0], af[mt][1], af[mt][2], af[mt][3], b2, b3);
                }
            }
        }
        __syncthreads();
        if (kt + 2 < NT) prefetch(kt + 2, kt & 1);
        CP_COMMIT();
    }

    #pragma unroll
    for (int mt = 0; mt < 4; mt++) {
        const int r0 = bm + wm*64 + mt*16 + gid;
        #pragma unroll
        for (int nt = 0; nt < 8; nt++) {
            const int cn = bn + wn*64 + nt*8 + tig*2;
            float bx = bias[cn], by = bias[cn+1];
            float2 v0 = make_float2(acc[mt][nt][0] + bx, acc[mt][nt][1] + by);
            float2 v1 = make_float2(acc[mt][nt][2] + bx, acc[mt][nt][3] + by);
            size_t o0 = (size_t)r0 * N + cn;
            size_t o1 = o0 + (size_t)8 * N;
            if (EPI == 0) {
                __half* C = (__half*)Cv;
                *(uint32_t*)(C + o0) = packh2(v0.x, v0.y);
                *(uint32_t*)(C + o1) = packh2(v1.x, v1.y);
            }
            if (EPI == 1) {
                __half* C = (__half*)Cv;
                *(uint32_t*)(C + o0) = packh2(fmaxf(v0.x, 0.f), fmaxf(v0.y, 0.f));
                *(uint32_t*)(C + o1) = packh2(fmaxf(v1.x, 0.f), fmaxf(v1.y, 0.f));
            }
            if (EPI == 2) {
                float* C = (float*)Cv;
                float2 r0v = *(const float2*)(res + o0);
                float2 r1v = *(const float2*)(res + o1);
                *(float2*)(C + o0) = make_float2(v0.x + r0v.x, v0.y + r0v.y);
                *(float2*)(C + o1) = make_float2(v1.x + r1v.x, v1.y + r1v.y);
            }
        }
    }
}

// ---------------- fp16 flash attention, 128 q-rows/CTA, reg-resident P ----
// 256 threads = 8 warps, warp w owns q-rows [w*16, w*16+16). K/V tiles (64)
// double-buffered; each loaded K/V tile now feeds 2x the mma work and CTA
// count halves -> half the K/V L2 traffic.
#define QS 72
#define QH (128*QS)             /* Q: 128 rows */
#define KH (64*QS)              /* K/V per stage: 64 rows */
#define ATT_SMEM ((QH + 2*KH + 2*KH) * 2 + 2*64*4)

__global__ void __launch_bounds__(256) attn_tc(
    const __half* __restrict__ QKV, const int* __restrict__ mask,
    __half* __restrict__ O)
{
    extern __shared__ __half hsm[];
    __half* q_s = hsm;
    __half* k_s = q_s + QH;            // 2 stages
    __half* v_s = k_s + 2*KH;          // 2 stages
    int*    m_s = (int*)(v_s + 2*KH);  // [2][64]

    const int tid = threadIdx.x, lane = tid & 31, w = tid >> 5;
    const int gid = lane >> 2, tig = lane & 3;
    const int qt = blockIdx.x, h = blockIdx.y, b = blockIdx.z;
    const __half* Qp = QKV + (size_t)b * SQ * DM3 + (size_t)h * DK;
    const __half* Kp = Qp + DM;
    const __half* Vp = Qp + 2*DM;
    const uint32_t qs_u = s2u(q_s);
    const uint32_t ks_u = s2u(k_s);
    const uint32_t vs_u = s2u(v_s);

    auto kv_prefetch = [&](int t, int buf) {
        #pragma unroll
        for (int i = 0; i < 2; i++) {
            int c = tid + i*256;               // 0..511
            int r = c >> 3, c8 = c & 7;
            size_t goff = (size_t)(t*64 + r) * DM3 + c8*8;
            uint32_t soff = (uint32_t)((buf*KH + r*QS + c8*8) * 2);
            cpasync16(ks_u + soff, Kp + goff);
            cpasync16(vs_u + soff, Vp + goff);
        }
    };

    kv_prefetch(0, 0); CP_COMMIT();

    // Q tile: 128 rows x 64 halves
    for (int i = tid; i < 128*8; i += 256) {
        int r = i >> 3, c8 = i & 7;
        *(uint4*)&q_s[r*QS + c8*8] =
            *(const uint4*)(Qp + (size_t)(qt*128 + r) * DM3 + c8*8);
    }

    const int a_row_l = (lane & 7) + (lane & 8);
    const int a_kcol  = ((lane >> 4) & 1) * 8;
    const uint32_t q_lane = (uint32_t)(((w*16 + a_row_l) * QS + a_kcol) * 2);
    const int b_row_l = lane & 15;
    const int b_col_l = ((lane >> 4) & 1) * 8;

    float o[8][4];
    #pragma unroll
    for (int nt = 0; nt < 8; nt++)
        #pragma unroll
        for (int i = 0; i < 4; i++) o[nt][i] = 0.f;
    float l0 = 0.f, l1 = 0.f;
    const int NTI = SQ/64;

    for (int t = 0; t < NTI; t++) {
        if (t + 1 < NTI) kv_prefetch(t + 1, (t + 1) & 1);
        CP_COMMIT();
        if (tid < 64) m_s[(t & 1)*64 + tid] = mask[b*SQ + t*64 + tid];
        CP_WAIT1();
        __syncthreads();
        const uint32_t kbase = ks_u + (uint32_t)((t & 1) * KH * 2);
        const uint32_t vbase = vs_u + (uint32_t)((t & 1) * KH * 2);
        const int* mb = m_s + (t & 1) * 64;

        // --- S = Q @ K^T ---
        float s[8][4];
        #pragma unroll
        for (int nt = 0; nt < 8; nt++)
            #pragma unroll
            for (int i = 0; i < 4; i++) s[nt][i] = 0.f;
        #pragma unroll
        for (int ks = 0; ks < 4; ks++) {
            uint32_t a0, a1, a2, a3;
            ldsm_x4(a0, a1, a2, a3, qs_u + q_lane + (uint32_t)(ks*32));
            #pragma unroll
            for (int p = 0; p < 4; p++) {
                uint32_t r0, r1, r2, r3;
                ldsm_x4(r0, r1, r2, r3,
                    kbase + (uint32_t)(((p*16 + b_row_l)*QS + ks*16 + b_col_l) * 2));
                mma16(s[2*p],   a0, a1, a2, a3, r0, r2);
                mma16(s[2*p+1], a0, a1, a2, a3, r1, r3);
            }
        }

        // --- scale + mask + exp -> half2 P frags (registers only) ---
        uint32_t ph[8][2];
        #pragma unroll
        for (int nt = 0; nt < 8; nt++) {
            const int c0 = nt*8 + tig*2;
            const bool z0 = (mb[c0] == 0), z1 = (mb[c0+1] == 0);
            float p0 = __expf(z0 ? -1e9f : s[nt][0] * 0.125f);
            float p1 = __expf(z1 ? -1e9f : s[nt][1] * 0.125f);
            float p2 = __expf(z0 ? -1e9f : s[nt][2] * 0.125f);
            float p3 = __expf(z1 ? -1e9f : s[nt][3] * 0.125f);
            l0 += p0 + p1;  l1 += p2 + p3;
            ph[nt][0] = packh2(p0, p1);
            ph[nt][1] = packh2(p2, p3);
        }

        // --- O += P @ V ---
        #pragma unroll
        for (int ks = 0; ks < 4; ks++) {
            uint32_t pa0 = ph[2*ks][0],   pa1 = ph[2*ks][1];
            uint32_t pa2 = ph[2*ks+1][0], pa3 = ph[2*ks+1][1];
            #pragma unroll
            for (int p = 0; p < 4; p++) {
                uint32_t r0, r1, r2, r3;
                ldsm_x4_t(r0, r1, r2, r3,
                    vbase + (uint32_t)(((ks*16 + b_row_l)*QS + p*16 + b_col_l) * 2));
                mma16(o[2*p],   pa0, pa1, pa2, pa3, r0, r1);
                mma16(o[2*p+1], pa0, pa1, pa2, pa3, r2, r3);
            }
        }
        __syncthreads();
    }

    l0 += __shfl_xor_sync(0xffffffffu, l0, 1);
    l0 += __shfl_xor_sync(0xffffffffu, l0, 2);
    l1 += __shfl_xor_sync(0xffffffffu, l1, 1);
    l1 += __shfl_xor_sync(0xffffffffu, l1, 2);
    const float n0 = 1.0f / l0, n1 = 1.0f / l1;
    #pragma unroll
    for (int nt = 0; nt < 8; nt++) {
        const int cn = h*DK + nt*8 + tig*2;
        size_t r0 = (size_t)(b*SQ + qt*128 + w*16 + gid) * DM + cn;
        size_t r1 = r0 + (size_t)8 * DM;
        *(uint32_t*)(O + r0) = packh2(o[nt][0]*n0, o[nt][1]*n0);
        *(uint32_t*)(O + r1) = packh2(o[nt][2]*n1, o[nt][3]*n1);
    }
}

// --------------------------------------------------------------------------
extern "C" void kernel_launch(void* const* d_in, const int* in_sizes, int n_in,
                              void* d_out, int out_size)
{
    const float* x    = (const float*)d_in[0];
    const int*   mask = (const int*)  d_in[1];
    const float* wq = (const float*)d_in[2],  *bq = (const float*)d_in[3];
    const float* wk = (const float*)d_in[4],  *bk = (const float*)d_in[5];
    const float* wv = (const float*)d_in[6],  *bv = (const float*)d_in[7];
    const float* wo = (const float*)d_in[8],  *bo = (const float*)d_in[9];
    const float* w1 = (const float*)d_in[10], *b1 = (const float*)d_in[11];
    const float* w2 = (const float*)d_in[12], *b2 = (const float*)d_in[13];
    const float* g1 = (const float*)d_in[14], *be1 = (const float*)d_in[15];
    const float* g2 = (const float*)d_in[16], *be2 = (const float*)d_in[17];
    float* out = (float*)d_out;

    __half *xn, *qkvh, *ctxh, *hbuf, *Wqh, *Wrh;
    float *x1, *Bq;
    cudaGetSymbolAddress((void**)&xn,   g_xn_h);
    cudaGetSymbolAddress((void**)&qkvh, g_qkv_h);
    cudaGetSymbolAddress((void**)&ctxh, g_ctx_h);
    cudaGetSymbolAddress((void**)&x1,   g_x1);
    cudaGetSymbolAddress((void**)&hbuf, g_h_h);
    cudaGetSymbolAddress((void**)&Wqh,  g_wqkvh);
    cudaGetSymbolAddress((void**)&Bq,   g_bqkv);
    cudaGetSymbolAddress((void**)&Wrh,  g_wrh);
    __half* wo_h = Wrh;
    __half* w1_h = Wrh + DM*DM;
    __half* w2_h = Wrh + DM*DM + DM*DFF;

    cudaFuncSetAttribute(gemm_tc<0>, cudaFuncAttributeMaxDynamicSharedMemorySize, GEMM_SMEM);
    cudaFuncSetAttribute(gemm_tc<1>, cudaFuncAttributeMaxDynamicSharedMemorySize, GEMM_SMEM);
    cudaFuncSetAttribute(gemm_tc<2>, cudaFuncAttributeMaxDynamicSharedMemorySize, GEMM_SMEM);
    cudaFuncSetAttribute(attn_tc,    cudaFuncAttributeMaxDynamicSharedMemorySize, ATT_SMEM);

    dim3 gQKV(DM3/128, ROWS/128);    // 24 x 32
    dim3 gProj(DM/128,  ROWS/128);   // 8 x 32
    dim3 gFF1 (DFF/128, ROWS/128);   // 32 x 32

    // 0) weight prep (half)
    pack_qkv<<<(3*(DM*DM/4) + 3*256 + 255)/256, 256>>>(wq, wk, wv, bq, bk, bv, Wqh, Bq);
    half_all<<<((NW4_WO + NW4_W1 + NW4_W2) + 255)/256, 256>>>(wo, w1, w2, Wrh);
    // 1) LN1 -> half
    ln_kernel<<<ROWS, 256>>>(x, g1, be1, xn);
    // 2) fused QKV projection (fp16 mma, half out)
    gemm_tc<0><<<gQKV, 128, GEMM_SMEM>>>(xn, Wqh, Bq, nullptr, qkvh, ROWS, DM3, DM);
    // 3) fused masked flash attention (fp16, 128 q-rows/CTA) -> ctx half
    attn_tc<<<dim3(SQ/128, NH, BATCH), 256, ATT_SMEM>>>(qkvh, mask, ctxh);
    // 4) out-proj + residual(x) -> x1 (f32)
    gemm_tc<2><<<gProj, 128, GEMM_SMEM>>>(ctxh, wo_h, bo, x, x1, ROWS, DM, DM);
    // 5) LN2 -> half
    ln_kernel<<<ROWS, 256>>>(x1, g2, be2, xn);
    // 6) FFN up + relu -> half
    gemm_tc<1><<<gFF1, 128, GEMM_SMEM>>>(xn, w1_h, b1, nullptr, hbuf, ROWS, DFF, DM);
    // 7) FFN down + residual(x1) -> out (f32)
    gemm_tc<2><<<gProj, 128, GEMM_SMEM>>>(hbuf, w2_h, b2, x1, out, ROWS, DM, DFF);
}

// round 12
// speedup vs baseline: 1.0665x; 1.0618x over previous
#include <cuda_runtime.h>
#include <cuda_fp16.h>
#include <math.h>
#include <stdint.h>

#define DM    1024
#define DFF   4096
#define SQ    2048
#define BATCH 2
#define ROWS  (BATCH*SQ)   /* 4096 */
#define DK    64
#define NH    16
#define DM3   (3*DM)

// ---------------- scratch (device globals; no allocation) ----------------
__device__ __half g_xn_h [ROWS*DM];
__device__ __half g_qkv_h[ROWS*DM3];
__device__ __half g_ctx_h[ROWS*DM];
__device__ float  g_x1   [ROWS*DM];
__device__ __half g_h_h  [ROWS*DFF];
__device__ __half g_wqkvh[DM*DM3];
__device__ float  g_bqkv [DM3];
__device__ __half g_wrh  [DM*DM + DM*DFF + DFF*DM];   // half wo|w1|w2

// ---------------- helpers -------------------------------------------------
__device__ __forceinline__ void mma16(float* c,
    uint32_t a0, uint32_t a1, uint32_t a2, uint32_t a3,
    uint32_t b0, uint32_t b1)
{
    asm volatile(
      "mma.sync.aligned.m16n8k16.row.col.f32.f16.f16.f32 "
      "{%0,%1,%2,%3},{%4,%5,%6,%7},{%8,%9},{%0,%1,%2,%3};"
      : "+f"(c[0]), "+f"(c[1]), "+f"(c[2]), "+f"(c[3])
      : "r"(a0), "r"(a1), "r"(a2), "r"(a3), "r"(b0), "r"(b1));
}
__device__ __forceinline__ void ldsm_x4(uint32_t& r0, uint32_t& r1,
                                        uint32_t& r2, uint32_t& r3, uint32_t addr)
{
    asm volatile("ldmatrix.sync.aligned.m8n8.x4.shared.b16 {%0,%1,%2,%3}, [%4];"
                 : "=r"(r0), "=r"(r1), "=r"(r2), "=r"(r3) : "r"(addr));
}
__device__ __forceinline__ void ldsm_x4_t(uint32_t& r0, uint32_t& r1,
                                          uint32_t& r2, uint32_t& r3, uint32_t addr)
{
    asm volatile("ldmatrix.sync.aligned.m8n8.x4.trans.shared.b16 {%0,%1,%2,%3}, [%4];"
                 : "=r"(r0), "=r"(r1), "=r"(r2), "=r"(r3) : "r"(addr));
}
__device__ __forceinline__ uint32_t s2u(const void* p) {
    uint32_t a;
    asm("{.reg .u64 t; cvta.to.shared.u64 t, %1; cvt.u32.u64 %0, t;}"
        : "=r"(a) : "l"(p));
    return a;
}
__device__ __forceinline__ void cpasync16(uint32_t dst, const void* src) {
    asm volatile("cp.async.cg.shared.global [%0], [%1], 16;" :: "r"(dst), "l"(src));
}
__device__ __forceinline__ uint32_t packh2(float a, float b) {
    __half2 h = __floats2half2_rn(a, b);
    return *(uint32_t*)&h;
}
#define CP_COMMIT() asm volatile("cp.async.commit_group;")
#define CP_WAIT2()  asm volatile("cp.async.wait_group 2;")
#define CP_WAIT1()  asm volatile("cp.async.wait_group 1;")

// ---------------- half-convert: wo|w1|w2 -> half --------------------------
#define NW4_WO (DM*DM/4)
#define NW4_W1 (DM*DFF/4)
#define NW4_W2 (DFF*DM/4)
__global__ void __launch_bounds__(256) half_all(
    const float* __restrict__ wo, const float* __restrict__ w1,
    const float* __restrict__ w2, __half* __restrict__ dst)
{
    int i = blockIdx.x * 256 + threadIdx.x;
    const float* src;
    int local;
    if (i < NW4_WO)                        { src = wo; local = i; }
    else if (i < NW4_WO + NW4_W1)          { src = w1; local = i - NW4_WO; }
    else if (i < NW4_WO + NW4_W1 + NW4_W2) { src = w2; local = i - NW4_WO - NW4_W1; }
    else return;
    float4 v = *(const float4*)(src + (size_t)local*4);
    *(uint2*)(dst + (size_t)i*4) = make_uint2(packh2(v.x, v.y), packh2(v.z, v.w));
}

// ---------------- pack wq|wk|wv -> half [1024][3072], biases f32 ----------
__global__ void __launch_bounds__(256) pack_qkv(
    const float* __restrict__ wq, const float* __restrict__ wk,
    const float* __restrict__ wv, const float* __restrict__ bq,
    const float* __restrict__ bk, const float* __restrict__ bv,
    __half* __restrict__ W, float* __restrict__ B)
{
    const int NW = 3 * (DM*DM/4);
    int idx = blockIdx.x * 256 + threadIdx.x;
    if (idx < NW) {
        int m  = idx / (DM*DM/4);
        int r  = idx - m * (DM*DM/4);
        int k  = r >> 8;
        int j4 = r & 255;
        const float* src = (m == 0) ? wq : (m == 1) ? wk : wv;
        float4 v = *(const float4*)(src + k*DM + j4*4);
        *(uint2*)(W + (size_t)k*DM3 + m*DM + j4*4) =
            make_uint2(packh2(v.x, v.y), packh2(v.z, v.w));
    } else if (idx < NW + 3*256) {
        int i = idx - NW;
        int m = i >> 8, j4 = i & 255;
        const float* src = (m == 0) ? bq : (m == 1) ? bk : bv;
        *(float4*)(B + m*DM + j4*4) = *(const float4*)(src + j4*4);
    }
}

// ---------------- LayerNorm (half output) ---------------------------------
__global__ void __launch_bounds__(256) ln_kernel(
    const float* __restrict__ X, const float* __restrict__ gamma,
    const float* __restrict__ beta, __half* __restrict__ Y)
{
    const int row = blockIdx.x, tid = threadIdx.x;
    const float* xr = X + (size_t)row * DM;
    float4 xv = *(const float4*)(xr + tid*4);
    float s  = xv.x + xv.y + xv.z + xv.w;
    float s2 = xv.x*xv.x + xv.y*xv.y + xv.z*xv.z + xv.w*xv.w;
    #pragma unroll
    for (int o = 16; o; o >>= 1) {
        s  += __shfl_xor_sync(0xffffffffu, s,  o);
        s2 += __shfl_xor_sync(0xffffffffu, s2, o);
    }
    __shared__ float sm1[8], sm2[8];
    if ((tid & 31) == 0) { sm1[tid>>5] = s; sm2[tid>>5] = s2; }
    __syncthreads();
    float ts = 0.f, ts2 = 0.f;
    #pragma unroll
    for (int i = 0; i < 8; i++) { ts += sm1[i]; ts2 += sm2[i]; }
    float mean = ts * (1.0f / DM);
    float var  = (ts2 - ts * mean) * (1.0f / (DM - 1));   // unbiased (ddof=1)
    float inv  = 1.0f / (sqrtf(var) + 1e-6f);             // eps OUTSIDE sqrt
    float4 g4 = *(const float4*)(gamma + tid*4);
    float4 b4 = *(const float4*)(beta  + tid*4);
    *(uint2*)(Y + (size_t)row * DM + tid*4) = make_uint2(
        packh2(g4.x * (xv.x - mean) * inv + b4.x,
               g4.y * (xv.y - mean) * inv + b4.y),
        packh2(g4.z * (xv.z - mean) * inv + b4.z,
               g4.w * (xv.w - mean) * inv + b4.w));
}

// ---------------- fp16 GEMM 128x128x32, 4-stage ring, single sync/kt ------
// 128 thr = 4 warps (2x2), 64x64 warp tile. Prefetch distance 3, wait_group 2.
// C = A@B + bias ; EPI: 0=half out (qkv), 1=relu half out, 2=+residual f32
#define BK 32
#define AS 40     /* halves; 80B row stride, ldsm banks 20r mod 32: conflict-free */
#define BS 136    /* halves; 272B row stride */
#define A_HALVES (128*AS)   /* 5120 */
#define B_HALVES (BK*BS)    /* 4352 */
#define NSTG 4
#define GEMM_SMEM (NSTG*(A_HALVES + B_HALVES)*2)   /* 75776 B */

template<int EPI>
__global__ void __launch_bounds__(128, 2) gemm_tc(
    const __half* __restrict__ A, const __half* __restrict__ Bm,
    const float* __restrict__ bias, const float* __restrict__ res,
    void* __restrict__ Cv, int M, int N, int K)
{
    extern __shared__ __half hsm[];
    __half* As = hsm;                        // [NSTG][A_HALVES]
    __half* Bs = hsm + NSTG*A_HALVES;        // [NSTG][B_HALVES]

    const int tid  = threadIdx.x;
    const int lane = tid & 31, wid = tid >> 5;
    const int wm = wid >> 1, wn = wid & 1;
    const int gid = lane >> 2, tig = lane & 3;
    const int bm = blockIdx.y * 128, bn = blockIdx.x * 128;

    // prefetch geometry (16B = 8 halves per cp.async)
    const int ar0 = tid >> 2, ac = (tid & 3) * 8;     // A: rows ar0+32i, 4 passes
    const int br0 = tid >> 4, bc = (tid & 15) * 8;    // B: rows br0+8i, 4 passes
    const uint32_t as_u = s2u(As);
    const uint32_t bs_u = s2u(Bs);

    const int NT = K >> 5;

    auto prefetch = [&](int kt) {
        const int buf = kt & (NSTG-1);
        const __half* Ag = A + (size_t)(bm + ar0) * K + kt*BK + ac;
        uint32_t ad = as_u + (uint32_t)(buf*A_HALVES + ar0*AS + ac) * 2;
        #pragma unroll
        for (int i = 0; i < 4; i++)
            cpasync16(ad + (uint32_t)(i*32*AS*2), Ag + (size_t)(i*32)*K);
        const __half* Bg = Bm + (size_t)(kt*BK + br0) * N + bn + bc;
        uint32_t bd = bs_u + (uint32_t)(buf*B_HALVES + br0*BS + bc) * 2;
        #pragma unroll
        for (int i = 0; i < 4; i++)
            cpasync16(bd + (uint32_t)(i*8*BS*2), Bg + (size_t)(i*8)*N);
    };

    // ldsm lane addressing
    const int a_row_l = (lane & 7) + (lane & 8);
    const int a_kcol  = ((lane >> 4) & 1) * 8;
    const uint32_t a_lane_off = (uint32_t)(((wm*64 + a_row_l) * AS + a_kcol) * 2);
    const int b_row_l = lane & 15;
    const int b_ncol  = ((lane >> 4) & 1) * 8;
    const uint32_t b_lane_off = (uint32_t)((b_row_l * BS + wn*64 + b_ncol) * 2);

    float acc[4][8][4];
    #pragma unroll
    for (int a = 0; a < 4; a++)
        #pragma unroll
        for (int b = 0; b < 8; b++)
            #pragma unroll
            for (int c = 0; c < 4; c++) acc[a][b][c] = 0.f;

    prefetch(0); CP_COMMIT();
    prefetch(1); CP_COMMIT();
    prefetch(2); CP_COMMIT();

    for (int kt = 0; kt < NT; kt++) {
        CP_WAIT2();                // <=2 groups pending -> stage kt landed
        __syncthreads();           // all warps done with stage (kt-1)%4 too
        const uint32_t abase = as_u + (uint32_t)((kt & (NSTG-1)) * A_HALVES * 2) + a_lane_off;
        const uint32_t bbase = bs_u + (uint32_t)((kt & (NSTG-1)) * B_HALVES * 2) + b_lane_off;
        #pragma unroll
        for (int ks = 0; ks < 2; ks++) {
            uint32_t af[4][4];
            #pragma unroll
            for (int mt = 0; mt < 4; mt++)
                ldsm_x4(af[mt][0], af[mt][1], af[mt][2], af[mt][3],
                        abase + (uint32_t)(mt*16*AS*2 + ks*32));
            #pragma unroll
            for (int p = 0; p < 4; p++) {
                uint32_t b0, b1, b2, b3;
                ldsm_x4_t(b0, b1, b2, b3,
                          bbase + (uint32_t)(ks*16*BS*2 + p*32));
                #pragma unroll
                for (int mt = 0; mt < 4; mt++) {
                    mma16(acc[mt][2*p],   af[mt][0], af[mt][1], af[mt][2], af[mt][3], b0, b1);
                    mma16(acc[mt][2*p+1], af[mt][0], af[mt][1], af[mt][2], af[mt][3], b2, b3);
                }
            }
        }
        // prefetch into stage (kt+3)%4 == (kt-1)%4: finished by all warps
        // before this iteration's barrier.
        if (kt + 3 < NT) prefetch(kt + 3);
        CP_COMMIT();
    }

    #pragma unroll
    for (int mt = 0; mt < 4; mt++) {
        const int r0 = bm + wm*64 + mt*16 + gid;
        #pragma unroll
        for (int nt = 0; nt < 8; nt++) {
            const int cn = bn + wn*64 + nt*8 + tig*2;
            float bx = bias[cn], by = bias[cn+1];
            float2 v0 = make_float2(acc[mt][nt][0] + bx, acc[mt][nt][1] + by);
            float2 v1 = make_float2(acc[mt][nt][2] + bx, acc[mt][nt][3] + by);
            size_t o0 = (size_t)r0 * N + cn;
            size_t o1 = o0 + (size_t)8 * N;
            if (EPI == 0) {
                __half* C = (__half*)Cv;
                *(uint32_t*)(C + o0) = packh2(v0.x, v0.y);
                *(uint32_t*)(C + o1) = packh2(v1.x, v1.y);
            }
            if (EPI == 1) {
                __half* C = (__half*)Cv;
                *(uint32_t*)(C + o0) = packh2(fmaxf(v0.x, 0.f), fmaxf(v0.y, 0.f));
                *(uint32_t*)(C + o1) = packh2(fmaxf(v1.x, 0.f), fmaxf(v1.y, 0.f));
            }
            if (EPI == 2) {
                float* C = (float*)Cv;
                float2 r0v = *(const float2*)(res + o0);
                float2 r1v = *(const float2*)(res + o1);
                *(float2*)(C + o0) = make_float2(v0.x + r0v.x, v0.y + r0v.y);
                *(float2*)(C + o1) = make_float2(v1.x + r1v.x, v1.y + r1v.y);
            }
        }
    }
}

// ---------------- fp16 flash attention (R8 verbatim: measured best) -------
#define QS 72
#define AQ_H (64*QS)
#define ATT_SMEM ((AQ_H + 2*AQ_H + 2*AQ_H) * 2 + 2*64*4)

__global__ void __launch_bounds__(128) attn_tc(
    const __half* __restrict__ QKV, const int* __restrict__ mask,
    __half* __restrict__ O)
{
    extern __shared__ __half hsm[];
    __half* q_s = hsm;
    __half* k_s = q_s + AQ_H;          // 2 stages
    __half* v_s = k_s + 2*AQ_H;        // 2 stages
    int*    m_s = (int*)(v_s + 2*AQ_H);// [2][64]

    const int tid = threadIdx.x, lane = tid & 31, w = tid >> 5;
    const int gid = lane >> 2, tig = lane & 3;
    const int qt = blockIdx.x, h = blockIdx.y, b = blockIdx.z;
    const __half* Qp = QKV + (size_t)b * SQ * DM3 + (size_t)h * DK;
    const __half* Kp = Qp + DM;
    const __half* Vp = Qp + 2*DM;
    const uint32_t qs_u = s2u(q_s);
    const uint32_t ks_u = s2u(k_s);
    const uint32_t vs_u = s2u(v_s);

    auto kv_prefetch = [&](int t, int buf) {
        #pragma unroll
        for (int i = 0; i < 4; i++) {
            int c = tid + i*128;
            int r = c >> 3, c8 = c & 7;
            size_t goff = (size_t)(t*64 + r) * DM3 + c8*8;
            uint32_t soff = (uint32_t)((buf*AQ_H + r*QS + c8*8) * 2);
            cpasync16(ks_u + soff, Kp + goff);
            cpasync16(vs_u + soff, Vp + goff);
        }
    };

    kv_prefetch(0, 0); CP_COMMIT();

    for (int i = tid; i < 64*8; i += 128) {
        int r = i >> 3, c8 = i & 7;
        *(uint4*)&q_s[r*QS + c8*8] =
            *(const uint4*)(Qp + (size_t)(qt*64 + r) * DM3 + c8*8);
    }

    const int a_row_l = (lane & 7) + (lane & 8);
    const int a_kcol  = ((lane >> 4) & 1) * 8;
    const uint32_t q_lane = (uint32_t)(((w*16 + a_row_l) * QS + a_kcol) * 2);
    const int b_row_l = lane & 15;
    const int b_col_l = ((lane >> 4) & 1) * 8;

    float o[8][4];
    #pragma unroll
    for (int nt = 0; nt < 8; nt++)
        #pragma unroll
        for (int i = 0; i < 4; i++) o[nt][i] = 0.f;
    float l0 = 0.f, l1 = 0.f;
    const int NTI = SQ/64;

    for (int t = 0; t < NTI; t++) {
        if (t + 1 < NTI) kv_prefetch(t + 1, (t + 1) & 1);
        CP_COMMIT();
        if (tid < 64) m_s[(t & 1)*64 + tid] = mask[b*SQ + t*64 + tid];
        CP_WAIT1();
        __syncthreads();
        const uint32_t kbase = ks_u + (uint32_t)((t & 1) * AQ_H * 2);
        const uint32_t vbase = vs_u + (uint32_t)((t & 1) * AQ_H * 2);
        const int* mb = m_s + (t & 1) * 64;

        float s[8][4];
        #pragma unroll
        for (int nt = 0; nt < 8; nt++)
            #pragma unroll
            for (int i = 0; i < 4; i++) s[nt][i] = 0.f;
        #pragma unroll
        for (int ks = 0; ks < 4; ks++) {
            uint32_t a0, a1, a2, a3;
            ldsm_x4(a0, a1, a2, a3, qs_u + q_lane + (uint32_t)(ks*32));
            #pragma unroll
            for (int p = 0; p < 4; p++) {
                uint32_t r0, r1, r2, r3;
                ldsm_x4(r0, r1, r2, r3,
                    kbase + (uint32_t)(((p*16 + b_row_l)*QS + ks*16 + b_col_l) * 2));
                mma16(s[2*p],   a0, a1, a2, a3, r0, r2);
                mma16(s[2*p+1], a0, a1, a2, a3, r1, r3);
            }
        }

        uint32_t ph[8][2];
        #pragma unroll
        for (int nt = 0; nt < 8; nt++) {
            const int c0 = nt*8 + tig*2;
            const bool z0 = (mb[c0] == 0), z1 = (mb[c0+1] == 0);
            float p0 = __expf(z0 ? -1e9f : s[nt][0] * 0.125f);
            float p1 = __expf(z1 ? -1e9f : s[nt][1] * 0.125f);
            float p2 = __expf(z0 ? -1e9f : s[nt][2] * 0.125f);
            float p3 = __expf(z1 ? -1e9f : s[nt][3] * 0.125f);
            l0 += p0 + p1;  l1 += p2 + p3;
            ph[nt][0] = packh2(p0, p1);
            ph[nt][1] = packh2(p2, p3);
        }

        #pragma unroll
        for (int ks = 0; ks < 4; ks++) {
            uint32_t pa0 = ph[2*ks][0],   pa1 = ph[2*ks][1];
            uint32_t pa2 = ph[2*ks+1][0], pa3 = ph[2*ks+1][1];
            #pragma unroll
            for (int p = 0; p < 4; p++) {
                uint32_t r0, r1, r2, r3;
                ldsm_x4_t(r0, r1, r2, r3,
                    vbase + (uint32_t)(((ks*16 + b_row_l)*QS + p*16 + b_col_l) * 2));
                mma16(o[2*p],   pa0, pa1, pa2, pa3, r0, r1);
                mma16(o[2*p+1], pa0, pa1, pa2, pa3, r2, r3);
            }
        }
        __syncthreads();
    }

    l0 += __shfl_xor_sync(0xffffffffu, l0, 1);
    l0 += __shfl_xor_sync(0xffffffffu, l0, 2);
    l1 += __shfl_xor_sync(0xffffffffu, l1, 1);
    l1 += __shfl_xor_sync(0xffffffffu, l1, 2);
    const float n0 = 1.0f / l0, n1 = 1.0f / l1;
    #pragma unroll
    for (int nt = 0; nt < 8; nt++) {
        const int cn = h*DK + nt*8 + tig*2;
        size_t r0 = (size_t)(b*SQ + qt*64 + w*16 + gid) * DM + cn;
        size_t r1 = r0 + (size_t)8 * DM;
        *(uint32_t*)(O + r0) = packh2(o[nt][0]*n0, o[nt][1]*n0);
        *(uint32_t*)(O + r1) = packh2(o[nt][2]*n1, o[nt][3]*n1);
    }
}

// --------------------------------------------------------------------------
extern "C" void kernel_launch(void* const* d_in, const int* in_sizes, int n_in,
                              void* d_out, int out_size)
{
    const float* x    = (const float*)d_in[0];
    const int*   mask = (const int*)  d_in[1];
    const float* wq = (const float*)d_in[2],  *bq = (const float*)d_in[3];
    const float* wk = (const float*)d_in[4],  *bk = (const float*)d_in[5];
    const float* wv = (const float*)d_in[6],  *bv = (const float*)d_in[7];
    const float* wo = (const float*)d_in[8],  *bo = (const float*)d_in[9];
    const float* w1 = (const float*)d_in[10], *b1 = (const float*)d_in[11];
    const float* w2 = (const float*)d_in[12], *b2 = (const float*)d_in[13];
    const float* g1 = (const float*)d_in[14], *be1 = (const float*)d_in[15];
    const float* g2 = (const float*)d_in[16], *be2 = (const float*)d_in[17];
    float* out = (float*)d_out;

    __half *xn, *qkvh, *ctxh, *hbuf, *Wqh, *Wrh;
    float *x1, *Bq;
    cudaGetSymbolAddress((void**)&xn,   g_xn_h);
    cudaGetSymbolAddress((void**)&qkvh, g_qkv_h);
    cudaGetSymbolAddress((void**)&ctxh, g_ctx_h);
    cudaGetSymbolAddress((void**)&x1,   g_x1);
    cudaGetSymbolAddress((void**)&hbuf, g_h_h);
    cudaGetSymbolAddress((void**)&Wqh,  g_wqkvh);
    cudaGetSymbolAddress((void**)&Bq,   g_bqkv);
    cudaGetSymbolAddress((void**)&Wrh,  g_wrh);
    __half* wo_h = Wrh;
    __half* w1_h = Wrh + DM*DM;
    __half* w2_h = Wrh + DM*DM + DM*DFF;

    cudaFuncSetAttribute(gemm_tc<0>, cudaFuncAttributeMaxDynamicSharedMemorySize, GEMM_SMEM);
    cudaFuncSetAttribute(gemm_tc<1>, cudaFuncAttributeMaxDynamicSharedMemorySize, GEMM_SMEM);
    cudaFuncSetAttribute(gemm_tc<2>, cudaFuncAttributeMaxDynamicSharedMemorySize, GEMM_SMEM);
    cudaFuncSetAttribute(attn_tc,    cudaFuncAttributeMaxDynamicSharedMemorySize, ATT_SMEM);

    dim3 gQKV(DM3/128, ROWS/128);    // 24 x 32
    dim3 gProj(DM/128,  ROWS/128);   // 8 x 32
    dim3 gFF1 (DFF/128, ROWS/128);   // 32 x 32

    // 0) weight prep (half)
    pack_qkv<<<(3*(DM*DM/4) + 3*256 + 255)/256, 256>>>(wq, wk, wv, bq, bk, bv, Wqh, Bq);
    half_all<<<((NW4_WO + NW4_W1 + NW4_W2) + 255)/256, 256>>>(wo, w1, w2, Wrh);
    // 1) LN1 -> half
    ln_kernel<<<ROWS, 256>>>(x, g1, be1, xn);
    // 2) fused QKV projection (fp16 mma, half out)
    gemm_tc<0><<<gQKV, 128, GEMM_SMEM>>>(xn, Wqh, Bq, nullptr, qkvh, ROWS, DM3, DM);
    // 3) fused masked flash attention (fp16) -> ctx half
    attn_tc<<<dim3(SQ/64, NH, BATCH), 128, ATT_SMEM>>>(qkvh, mask, ctxh);
    // 4) out-proj + residual(x) -> x1 (f32)
    gemm_tc<2><<<gProj, 128, GEMM_SMEM>>>(ctxh, wo_h, bo, x, x1, ROWS, DM, DM);
    // 5) LN2 -> half
    ln_kernel<<<ROWS, 256>>>(x1, g2, be2, xn);
    // 6) FFN up + relu -> half
    gemm_tc<1><<<gFF1, 128, GEMM_SMEM>>>(xn, w1_h, b1, nullptr, hbuf, ROWS, DFF, DM);
    // 7) FFN down + residual(x1) -> out (f32)
    gemm_tc<2><<<gProj, 128, GEMM_SMEM>>>(hbuf, w2_h, b2, x1, out, ROWS, DM, DFF);
}

// round 13
// speedup vs baseline: 1.0747x; 1.0078x over previous
#include <cuda_runtime.h>
#include <cuda_fp16.h>
#include <math.h>
#include <stdint.h>

#define DM    1024
#define DFF   4096
#define SQ    2048
#define BATCH 2
#define ROWS  (BATCH*SQ)   /* 4096 */
#define DK    64
#define NH    16
#define DM3   (3*DM)

// ---------------- scratch (device globals; no allocation) ----------------
__device__ __half g_xn_h [ROWS*DM];
__device__ __half g_qkv_h[ROWS*DM3];
__device__ __half g_ctx_h[ROWS*DM];
__device__ float  g_x1   [ROWS*DM];
__device__ __half g_h_h  [ROWS*DFF];
__device__ __half g_wqkvh[DM*DM3];
__device__ float  g_bqkv [DM3];
__device__ __half g_wrh  [DM*DM + DM*DFF + DFF*DM];   // half wo|w1|w2

// ---------------- helpers -------------------------------------------------
__device__ __forceinline__ void mma16(float* c,
    uint32_t a0, uint32_t a1, uint32_t a2, uint32_t a3,
    uint32_t b0, uint32_t b1)
{
    asm volatile(
      "mma.sync.aligned.m16n8k16.row.col.f32.f16.f16.f32 "
      "{%0,%1,%2,%3},{%4,%5,%6,%7},{%8,%9},{%0,%1,%2,%3};"
      : "+f"(c[0]), "+f"(c[1]), "+f"(c[2]), "+f"(c[3])
      : "r"(a0), "r"(a1), "r"(a2), "r"(a3), "r"(b0), "r"(b1));
}
__device__ __forceinline__ void ldsm_x4(uint32_t& r0, uint32_t& r1,
                                        uint32_t& r2, uint32_t& r3, uint32_t addr)
{
    asm volatile("ldmatrix.sync.aligned.m8n8.x4.shared.b16 {%0,%1,%2,%3}, [%4];"
                 : "=r"(r0), "=r"(r1), "=r"(r2), "=r"(r3) : "r"(addr));
}
__device__ __forceinline__ void ldsm_x4_t(uint32_t& r0, uint32_t& r1,
                                          uint32_t& r2, uint32_t& r3, uint32_t addr)
{
    asm volatile("ldmatrix.sync.aligned.m8n8.x4.trans.shared.b16 {%0,%1,%2,%3}, [%4];"
                 : "=r"(r0), "=r"(r1), "=r"(r2), "=r"(r3) : "r"(addr));
}
__device__ __forceinline__ uint32_t s2u(const void* p) {
    uint32_t a;
    asm("{.reg .u64 t; cvta.to.shared.u64 t, %1; cvt.u32.u64 %0, t;}"
        : "=r"(a) : "l"(p));
    return a;
}
__device__ __forceinline__ void cpasync16(uint32_t dst, const void* src) {
    asm volatile("cp.async.cg.shared.global [%0], [%1], 16;" :: "r"(dst), "l"(src));
}
__device__ __forceinline__ uint32_t packh2(float a, float b) {
    __half2 h = __floats2half2_rn(a, b);
    return *(uint32_t*)&h;
}
#define CP_COMMIT() asm volatile("cp.async.commit_group;")
#define CP_WAIT2()  asm volatile("cp.async.wait_group 2;")
#define CP_WAIT1()  asm volatile("cp.async.wait_group 1;")

// ---------------- half-convert: wo|w1|w2 -> half --------------------------
#define NW4_WO (DM*DM/4)
#define NW4_W1 (DM*DFF/4)
#define NW4_W2 (DFF*DM/4)
__global__ void __launch_bounds__(256) half_all(
    const float* __restrict__ wo, const float* __restrict__ w1,
    const float* __restrict__ w2, __half* __restrict__ dst)
{
    int i = blockIdx.x * 256 + threadIdx.x;
    const float* src;
    int local;
    if (i < NW4_WO)                        { src = wo; local = i; }
    else if (i < NW4_WO + NW4_W1)          { src = w1; local = i - NW4_WO; }
    else if (i < NW4_WO + NW4_W1 + NW4_W2) { src = w2; local = i - NW4_WO - NW4_W1; }
    else return;
    float4 v = *(const float4*)(src + (size_t)local*4);
    *(uint2*)(dst + (size_t)i*4) = make_uint2(packh2(v.x, v.y), packh2(v.z, v.w));
}

// ---------------- pack wq|wk|wv -> half [1024][3072], biases f32 ----------
__global__ void __launch_bounds__(256) pack_qkv(
    const float* __restrict__ wq, const float* __restrict__ wk,
    const float* __restrict__ wv, const float* __restrict__ bq,
    const float* __restrict__ bk, const float* __restrict__ bv,
    __half* __restrict__ W, float* __restrict__ B)
{
    const int NW = 3 * (DM*DM/4);
    int idx = blockIdx.x * 256 + threadIdx.x;
    if (idx < NW) {
        int m  = idx / (DM*DM/4);
        int r  = idx - m * (DM*DM/4);
        int k  = r >> 8;
        int j4 = r & 255;
        const float* src = (m == 0) ? wq : (m == 1) ? wk : wv;
        float4 v = *(const float4*)(src + k*DM + j4*4);
        *(uint2*)(W + (size_t)k*DM3 + m*DM + j4*4) =
            make_uint2(packh2(v.x, v.y), packh2(v.z, v.w));
    } else if (idx < NW + 3*256) {
        int i = idx - NW;
        int m = i >> 8, j4 = i & 255;
        const float* src = (m == 0) ? bq : (m == 1) ? bk : bv;
        *(float4*)(B + m*DM + j4*4) = *(const float4*)(src + j4*4);
    }
}

// ---------------- LayerNorm (half output) ---------------------------------
__global__ void __launch_bounds__(256) ln_kernel(
    const float* __restrict__ X, const float* __restrict__ gamma,
    const float* __restrict__ beta, __half* __restrict__ Y)
{
    const int row = blockIdx.x, tid = threadIdx.x;
    const float* xr = X + (size_t)row * DM;
    float4 xv = *(const float4*)(xr + tid*4);
    float s  = xv.x + xv.y + xv.z + xv.w;
    float s2 = xv.x*xv.x + xv.y*xv.y + xv.z*xv.z + xv.w*xv.w;
    #pragma unroll
    for (int o = 16; o; o >>= 1) {
        s  += __shfl_xor_sync(0xffffffffu, s,  o);
        s2 += __shfl_xor_sync(0xffffffffu, s2, o);
    }
    __shared__ float sm1[8], sm2[8];
    if ((tid & 31) == 0) { sm1[tid>>5] = s; sm2[tid>>5] = s2; }
    __syncthreads();
    float ts = 0.f, ts2 = 0.f;
    #pragma unroll
    for (int i = 0; i < 8; i++) { ts += sm1[i]; ts2 += sm2[i]; }
    float mean = ts * (1.0f / DM);
    float var  = (ts2 - ts * mean) * (1.0f / (DM - 1));   // unbiased (ddof=1)
    float inv  = 1.0f / (sqrtf(var) + 1e-6f);             // eps OUTSIDE sqrt
    float4 g4 = *(const float4*)(gamma + tid*4);
    float4 b4 = *(const float4*)(beta  + tid*4);
    *(uint2*)(Y + (size_t)row * DM + tid*4) = make_uint2(
        packh2(g4.x * (xv.x - mean) * inv + b4.x,
               g4.y * (xv.y - mean) * inv + b4.y),
        packh2(g4.z * (xv.z - mean) * inv + b4.z,
               g4.w * (xv.w - mean) * inv + b4.w));
}

// ---------------- fp16 GEMM 128x128, 6-stage ring, 1 sync per 2 k-tiles ---
// 128 thr = 4 warps (2x2), 64x64 warp tile, BK=32 per stage.
// C = A@B + bias ; EPI: 0=half out (qkv), 1=relu half out, 2=+residual f32
#define BK 32
#define AS 40     /* halves; 80B row stride: conflict-free ldsm */
#define BS 136    /* halves; 272B row stride */
#define A_HALVES (128*AS)   /* 5120 */
#define B_HALVES (BK*BS)    /* 4352 */
#define NSTG 6
#define GEMM_SMEM (NSTG*(A_HALVES + B_HALVES)*2)   /* 113664 B; 2 CTAs = 222KB */

template<int EPI>
__global__ void __launch_bounds__(128, 2) gemm_tc(
    const __half* __restrict__ A, const __half* __restrict__ Bm,
    const float* __restrict__ bias, const float* __restrict__ res,
    void* __restrict__ Cv, int M, int N, int K)
{
    extern __shared__ __half hsm[];
    __half* As = hsm;                        // [NSTG][A_HALVES]
    __half* Bs = hsm + NSTG*A_HALVES;        // [NSTG][B_HALVES]

    const int tid  = threadIdx.x;
    const int lane = tid & 31, wid = tid >> 5;
    const int wm = wid >> 1, wn = wid & 1;
    const int gid = lane >> 2, tig = lane & 3;
    const int bm = blockIdx.y * 128, bn = blockIdx.x * 128;

    const int ar0 = tid >> 2, ac = (tid & 3) * 8;     // A: rows ar0+32i
    const int br0 = tid >> 4, bc = (tid & 15) * 8;    // B: rows br0+8i
    const uint32_t as_u = s2u(As);
    const uint32_t bs_u = s2u(Bs);

    const int NT = K >> 5;      // K always multiple of 64 -> NT even

    auto prefetch = [&](int kt) {
        const int buf = kt % NSTG;
        const __half* Ag = A + (size_t)(bm + ar0) * K + kt*BK + ac;
        uint32_t ad = as_u + (uint32_t)(buf*A_HALVES + ar0*AS + ac) * 2;
        #pragma unroll
        for (int i = 0; i < 4; i++)
            cpasync16(ad + (uint32_t)(i*32*AS*2), Ag + (size_t)(i*32)*K);
        const __half* Bg = Bm + (size_t)(kt*BK + br0) * N + bn + bc;
        uint32_t bd = bs_u + (uint32_t)(buf*B_HALVES + br0*BS + bc) * 2;
        #pragma unroll
        for (int i = 0; i < 4; i++)
            cpasync16(bd + (uint32_t)(i*8*BS*2), Bg + (size_t)(i*8)*N);
    };

    const int a_row_l = (lane & 7) + (lane & 8);
    const int a_kcol  = ((lane >> 4) & 1) * 8;
    const uint32_t a_lane_off = (uint32_t)(((wm*64 + a_row_l) * AS + a_kcol) * 2);
    const int b_row_l = lane & 15;
    const int b_ncol  = ((lane >> 4) & 1) * 8;
    const uint32_t b_lane_off = (uint32_t)((b_row_l * BS + wn*64 + b_ncol) * 2);

    float acc[4][8][4];
    #pragma unroll
    for (int a = 0; a < 4; a++)
        #pragma unroll
        for (int b = 0; b < 8; b++)
            #pragma unroll
            for (int c = 0; c < 4; c++) acc[a][b][c] = 0.f;

    prefetch(0); CP_COMMIT();
    prefetch(1); CP_COMMIT();
    prefetch(2); CP_COMMIT();
    prefetch(3); CP_COMMIT();

    for (int kt = 0; kt < NT; kt += 2) {
        CP_WAIT2();                // stages kt, kt+1 landed (kt+2, kt+3 in flight)
        __syncthreads();           // all warps done with stages kt-2, kt-1 slots
        #pragma unroll
        for (int st = 0; st < 2; st++) {
            const int buf = (kt + st) % NSTG;
            const uint32_t abase = as_u + (uint32_t)(buf * A_HALVES * 2) + a_lane_off;
            const uint32_t bbase = bs_u + (uint32_t)(buf * B_HALVES * 2) + b_lane_off;
            #pragma unroll
            for (int ks = 0; ks < 2; ks++) {
                uint32_t af[4][4];
                #pragma unroll
                for (int mt = 0; mt < 4; mt++)
                    ldsm_x4(af[mt][0], af[mt][1], af[mt][2], af[mt][3],
                            abase + (uint32_t)(mt*16*AS*2 + ks*32));
                #pragma unroll
                for (int p = 0; p < 4; p++) {
                    uint32_t b0, b1, b2, b3;
                    ldsm_x4_t(b0, b1, b2, b3,
                              bbase + (uint32_t)(ks*16*BS*2 + p*32));
                    #pragma unroll
                    for (int mt = 0; mt < 4; mt++) {
                        mma16(acc[mt][2*p],   af[mt][0], af[mt][1], af[mt][2], af[mt][3], b0, b1);
                        mma16(acc[mt][2*p+1], af[mt][0], af[mt][1], af[mt][2], af[mt][3], b2, b3);
                    }
                }
            }
        }
        // prefetch into slots (kt+4)%6 == (kt-2)%6 and (kt+5)%6 == (kt-1)%6:
        // those stages were computed in the previous iteration; every warp
        // passed this iteration's top barrier after finishing them.
        if (kt + 4 < NT) prefetch(kt + 4);
        CP_COMMIT();
        if (kt + 5 < NT) prefetch(kt + 5);
        CP_COMMIT();
    }

    #pragma unroll
    for (int mt = 0; mt < 4; mt++) {
        const int r0 = bm + wm*64 + mt*16 + gid;
        #pragma unroll
        for (int nt = 0; nt < 8; nt++) {
            const int cn = bn + wn*64 + nt*8 + tig*2;
            float bx = bias[cn], by = bias[cn+1];
            float2 v0 = make_float2(acc[mt][nt][0] + bx, acc[mt][nt][1] + by);
            float2 v1 = make_float2(acc[mt][nt][2] + bx, acc[mt][nt][3] + by);
            size_t o0 = (size_t)r0 * N + cn;
            size_t o1 = o0 + (size_t)8 * N;
            if (EPI == 0) {
                __half* C = (__half*)Cv;
                *(uint32_t*)(C + o0) = packh2(v0.x, v0.y);
                *(uint32_t*)(C + o1) = packh2(v1.x, v1.y);
            }
            if (EPI == 1) {
                __half* C = (__half*)Cv;
                *(uint32_t*)(C + o0) = packh2(fmaxf(v0.x, 0.f), fmaxf(v0.y, 0.f));
                *(uint32_t*)(C + o1) = packh2(fmaxf(v1.x, 0.f), fmaxf(v1.y, 0.f));
            }
            if (EPI == 2) {
                float* C = (float*)Cv;
                float2 r0v = *(const float2*)(res + o0);
                float2 r1v = *(const float2*)(res + o1);
                *(float2*)(C + o0) = make_float2(v0.x + r0v.x, v0.y + r0v.y);
                *(float2*)(C + o1) = make_float2(v1.x + r1v.x, v1.y + r1v.y);
            }
        }
    }
}

// ---------------- fp16 flash attention (R8 verbatim: measured best) -------
#define QS 72
#define AQ_H (64*QS)
#define ATT_SMEM ((AQ_H + 2*AQ_H + 2*AQ_H) * 2 + 2*64*4)

__global__ void __launch_bounds__(128) attn_tc(
    const __half* __restrict__ QKV, const int* __restrict__ mask,
    __half* __restrict__ O)
{
    extern __shared__ __half hsm[];
    __half* q_s = hsm;
    __half* k_s = q_s + AQ_H;          // 2 stages
    __half* v_s = k_s + 2*AQ_H;        // 2 stages
    int*    m_s = (int*)(v_s + 2*AQ_H);// [2][64]

    const int tid = threadIdx.x, lane = tid & 31, w = tid >> 5;
    const int gid = lane >> 2, tig = lane & 3;
    const int qt = blockIdx.x, h = blockIdx.y, b = blockIdx.z;
    const __half* Qp = QKV + (size_t)b * SQ * DM3 + (size_t)h * DK;
    const __half* Kp = Qp + DM;
    const __half* Vp = Qp + 2*DM;
    const uint32_t qs_u = s2u(q_s);
    const uint32_t ks_u = s2u(k_s);
    const uint32_t vs_u = s2u(v_s);

    auto kv_prefetch = [&](int t, int buf) {
        #pragma unroll
        for (int i = 0; i < 4; i++) {
            int c = tid + i*128;
            int r = c >> 3, c8 = c & 7;
            size_t goff = (size_t)(t*64 + r) * DM3 + c8*8;
            uint32_t soff = (uint32_t)((buf*AQ_H + r*QS + c8*8) * 2);
            cpasync16(ks_u + soff, Kp + goff);
            cpasync16(vs_u + soff, Vp + goff);
        }
    };

    kv_prefetch(0, 0); CP_COMMIT();

    for (int i = tid; i < 64*8; i += 128) {
        int r = i >> 3, c8 = i & 7;
        *(uint4*)&q_s[r*QS + c8*8] =
            *(const uint4*)(Qp + (size_t)(qt*64 + r) * DM3 + c8*8);
    }

    const int a_row_l = (lane & 7) + (lane & 8);
    const int a_kcol  = ((lane >> 4) & 1) * 8;
    const uint32_t q_lane = (uint32_t)(((w*16 + a_row_l) * QS + a_kcol) * 2);
    const int b_row_l = lane & 15;
    const int b_col_l = ((lane >> 4) & 1) * 8;

    float o[8][4];
    #pragma unroll
    for (int nt = 0; nt < 8; nt++)
        #pragma unroll
        for (int i = 0; i < 4; i++) o[nt][i] = 0.f;
    float l0 = 0.f, l1 = 0.f;
    const int NTI = SQ/64;

    for (int t = 0; t < NTI; t++) {
        if (t + 1 < NTI) kv_prefetch(t + 1, (t + 1) & 1);
        CP_COMMIT();
        if (tid < 64) m_s[(t & 1)*64 + tid] = mask[b*SQ + t*64 + tid];
        CP_WAIT1();
        __syncthreads();
        const uint32_t kbase = ks_u + (uint32_t)((t & 1) * AQ_H * 2);
        const uint32_t vbase = vs_u + (uint32_t)((t & 1) * AQ_H * 2);
        const int* mb = m_s + (t & 1) * 64;

        float s[8][4];
        #pragma unroll
        for (int nt = 0; nt < 8; nt++)
            #pragma unroll
            for (int i = 0; i < 4; i++) s[nt][i] = 0.f;
        #pragma unroll
        for (int ks = 0; ks < 4; ks++) {
            uint32_t a0, a1, a2, a3;
            ldsm_x4(a0, a1, a2, a3, qs_u + q_lane + (uint32_t)(ks*32));
            #pragma unroll
            for (int p = 0; p < 4; p++) {
                uint32_t r0, r1, r2, r3;
                ldsm_x4(r0, r1, r2, r3,
                    kbase + (uint32_t)(((p*16 + b_row_l)*QS + ks*16 + b_col_l) * 2));
                mma16(s[2*p],   a0, a1, a2, a3, r0, r2);
                mma16(s[2*p+1], a0, a1, a2, a3, r1, r3);
            }
        }

        uint32_t ph[8][2];
        #pragma unroll
        for (int nt = 0; nt < 8; nt++) {
            const int c0 = nt*8 + tig*2;
            const bool z0 = (mb[c0] == 0), z1 = (mb[c0+1] == 0);
            float p0 = __expf(z0 ? -1e9f : s[nt][0] * 0.125f);
            float p1 = __expf(z1 ? -1e9f : s[nt][1] * 0.125f);
            float p2 = __expf(z0 ? -1e9f : s[nt][2] * 0.125f);
            float p3 = __expf(z1 ? -1e9f : s[nt][3] * 0.125f);
            l0 += p0 + p1;  l1 += p2 + p3;
            ph[nt][0] = packh2(p0, p1);
            ph[nt][1] = packh2(p2, p3);
        }

        #pragma unroll
        for (int ks = 0; ks < 4; ks++) {
            uint32_t pa0 = ph[2*ks][0],   pa1 = ph[2*ks][1];
            uint32_t pa2 = ph[2*ks+1][0], pa3 = ph[2*ks+1][1];
            #pragma unroll
            for (int p = 0; p < 4; p++) {
                uint32_t r0, r1, r2, r3;
                ldsm_x4_t(r0, r1, r2, r3,
                    vbase + (uint32_t)(((ks*16 + b_row_l)*QS + p*16 + b_col_l) * 2));
                mma16(o[2*p],   pa0, pa1, pa2, pa3, r0, r1);
                mma16(o[2*p+1], pa0, pa1, pa2, pa3, r2, r3);
            }
        }
        __syncthreads();
    }

    l0 += __shfl_xor_sync(0xffffffffu, l0, 1);
    l0 += __shfl_xor_sync(0xffffffffu, l0, 2);
    l1 += __shfl_xor_sync(0xffffffffu, l1, 1);
    l1 += __shfl_xor_sync(0xffffffffu, l1, 2);
    const float n0 = 1.0f / l0, n1 = 1.0f / l1;
    #pragma unroll
    for (int nt = 0; nt < 8; nt++) {
        const int cn = h*DK + nt*8 + tig*2;
        size_t r0 = (size_t)(b*SQ + qt*64 + w*16 + gid) * DM + cn;
        size_t r1 = r0 + (size_t)8 * DM;
        *(uint32_t*)(O + r0) = packh2(o[nt][0]*n0, o[nt][1]*n0);
        *(uint32_t*)(O + r1) = packh2(o[nt][2]*n1, o[nt][3]*n1);
    }
}

// --------------------------------------------------------------------------
extern "C" void kernel_launch(void* const* d_in, const int* in_sizes, int n_in,
                              void* d_out, int out_size)
{
    const float* x    = (const float*)d_in[0];
    const int*   mask = (const int*)  d_in[1];
    const float* wq = (const float*)d_in[2],  *bq = (const float*)d_in[3];
    const float* wk = (const float*)d_in[4],  *bk = (const float*)d_in[5];
    const float* wv = (const float*)d_in[6],  *bv = (const float*)d_in[7];
    const float* wo = (const float*)d_in[8],  *bo = (const float*)d_in[9];
    const float* w1 = (const float*)d_in[10], *b1 = (const float*)d_in[11];
    const float* w2 = (const float*)d_in[12], *b2 = (const float*)d_in[13];
    const float* g1 = (const float*)d_in[14], *be1 = (const float*)d_in[15];
    const float* g2 = (const float*)d_in[16], *be2 = (const float*)d_in[17];
    float* out = (float*)d_out;

    __half *xn, *qkvh, *ctxh, *hbuf, *Wqh, *Wrh;
    float *x1, *Bq;
    cudaGetSymbolAddress((void**)&xn,   g_xn_h);
    cudaGetSymbolAddress((void**)&qkvh, g_qkv_h);
    cudaGetSymbolAddress((void**)&ctxh, g_ctx_h);
    cudaGetSymbolAddress((void**)&x1,   g_x1);
    cudaGetSymbolAddress((void**)&hbuf, g_h_h);
    cudaGetSymbolAddress((void**)&Wqh,  g_wqkvh);
    cudaGetSymbolAddress((void**)&Bq,   g_bqkv);
    cudaGetSymbolAddress((void**)&Wrh,  g_wrh);
    __half* wo_h = Wrh;
    __half* w1_h = Wrh + DM*DM;
    __half* w2_h = Wrh + DM*DM + DM*DFF;

    cudaFuncSetAttribute(gemm_tc<0>, cudaFuncAttributeMaxDynamicSharedMemorySize, GEMM_SMEM);
    cudaFuncSetAttribute(gemm_tc<1>, cudaFuncAttributeMaxDynamicSharedMemorySize, GEMM_SMEM);
    cudaFuncSetAttribute(gemm_tc<2>, cudaFuncAttributeMaxDynamicSharedMemorySize, GEMM_SMEM);
    cudaFuncSetAttribute(attn_tc,    cudaFuncAttributeMaxDynamicSharedMemorySize, ATT_SMEM);

    dim3 gQKV(DM3/128, ROWS/128);    // 24 x 32
    dim3 gProj(DM/128,  ROWS/128);   // 8 x 32
    dim3 gFF1 (DFF/128, ROWS/128);   // 32 x 32

    // 0) weight prep (half)
    pack_qkv<<<(3*(DM*DM/4) + 3*256 + 255)/256, 256>>>(wq, wk, wv, bq, bk, bv, Wqh, Bq);
    half_all<<<((NW4_WO + NW4_W1 + NW4_W2) + 255)/256, 256>>>(wo, w1, w2, Wrh);
    // 1) LN1 -> half
    ln_kernel<<<ROWS, 256>>>(x, g1, be1, xn);
    // 2) fused QKV projection (fp16 mma, half out)
    gemm_tc<0><<<gQKV, 128, GEMM_SMEM>>>(xn, Wqh, Bq, nullptr, qkvh, ROWS, DM3, DM);
    // 3) fused masked flash attention (fp16) -> ctx half
    attn_tc<<<dim3(SQ/64, NH, BATCH), 128, ATT_SMEM>>>(qkvh, mask, ctxh);
    // 4) out-proj + residual(x) -> x1 (f32)
    gemm_tc<2><<<gProj, 128, GEMM_SMEM>>>(ctxh, wo_h, bo, x, x1, ROWS, DM, DM);
    // 5) LN2 -> half
    ln_kernel<<<ROWS, 256>>>(x1, g2, be2, xn);
    // 6) FFN up + relu -> half
    gemm_tc<1><<<gFF1, 128, GEMM_SMEM>>>(xn, w1_h, b1, nullptr, hbuf, ROWS, DFF, DM);
    // 7) FFN down + residual(x1) -> out (f32)
    gemm_tc<2><<<gProj, 128, GEMM_SMEM>>>(hbuf, w2_h, b2, x1, out, ROWS, DM, DFF);
}

// round 14
// speedup vs baseline: 1.0912x; 1.0153x over previous
#include <cuda_runtime.h>
#include <cuda_fp16.h>
#include <math.h>
#include <stdint.h>

#define DM    1024
#define DFF   4096
#define SQ    2048
#define BATCH 2
#define ROWS  (BATCH*SQ)   /* 4096 */
#define DK    64
#define NH    16
#define DM3   (3*DM)

// ---------------- scratch (device globals; no allocation) ----------------
__device__ __half g_xn_h [ROWS*DM];
__device__ __half g_qkv_h[ROWS*DM3];
__device__ __half g_ctx_h[ROWS*DM];
__device__ float  g_x1   [ROWS*DM];
__device__ __half g_h_h  [ROWS*DFF];
__device__ __half g_wqkvh[DM*DM3];
__device__ float  g_bqkv [DM3];
__device__ __half g_wrh  [DM*DM + DM*DFF + DFF*DM];   // half wo|w1|w2

// ---------------- helpers -------------------------------------------------
__device__ __forceinline__ void mma16(float* c,
    uint32_t a0, uint32_t a1, uint32_t a2, uint32_t a3,
    uint32_t b0, uint32_t b1)
{
    asm volatile(
      "mma.sync.aligned.m16n8k16.row.col.f32.f16.f16.f32 "
      "{%0,%1,%2,%3},{%4,%5,%6,%7},{%8,%9},{%0,%1,%2,%3};"
      : "+f"(c[0]), "+f"(c[1]), "+f"(c[2]), "+f"(c[3])
      : "r"(a0), "r"(a1), "r"(a2), "r"(a3), "r"(b0), "r"(b1));
}
__device__ __forceinline__ void ldsm_x4(uint32_t& r0, uint32_t& r1,
                                        uint32_t& r2, uint32_t& r3, uint32_t addr)
{
    asm volatile("ldmatrix.sync.aligned.m8n8.x4.shared.b16 {%0,%1,%2,%3}, [%4];"
                 : "=r"(r0), "=r"(r1), "=r"(r2), "=r"(r3) : "r"(addr));
}
__device__ __forceinline__ void ldsm_x4_t(uint32_t& r0, uint32_t& r1,
                                          uint32_t& r2, uint32_t& r3, uint32_t addr)
{
    asm volatile("ldmatrix.sync.aligned.m8n8.x4.trans.shared.b16 {%0,%1,%2,%3}, [%4];"
                 : "=r"(r0), "=r"(r1), "=r"(r2), "=r"(r3) : "r"(addr));
}
__device__ __forceinline__ uint32_t s2u(const void* p) {
    uint32_t a;
    asm("{.reg .u64 t; cvta.to.shared.u64 t, %1; cvt.u32.u64 %0, t;}"
        : "=r"(a) : "l"(p));
    return a;
}
__device__ __forceinline__ void cpasync16(uint32_t dst, const void* src) {
    asm volatile("cp.async.cg.shared.global [%0], [%1], 16;" :: "r"(dst), "l"(src));
}
__device__ __forceinline__ uint32_t packh2(float a, float b) {
    __half2 h = __floats2half2_rn(a, b);
    return *(uint32_t*)&h;
}
#define CP_COMMIT() asm volatile("cp.async.commit_group;")
#define CP_WAIT2()  asm volatile("cp.async.wait_group 2;")
#define CP_WAIT1()  asm volatile("cp.async.wait_group 1;")

// ---------------- fused weight prep: qkv pack + biases + wo|w1|w2 ---------
#define NWQ   (3*(DM*DM/4))
#define NB4   (3*256)
#define NW4_WO (DM*DM/4)
#define NW4_W1 (DM*DFF/4)
#define NW4_W2 (DFF*DM/4)
#define NW4_R  (NW4_WO + NW4_W1 + NW4_W2)
#define PREP_TOTAL (NWQ + NB4 + NW4_R)

__global__ void __launch_bounds__(256) prep_all(
    const float* __restrict__ wq, const float* __restrict__ wk,
    const float* __restrict__ wv, const float* __restrict__ bq,
    const float* __restrict__ bk, const float* __restrict__ bv,
    const float* __restrict__ wo, const float* __restrict__ w1,
    const float* __restrict__ w2,
    __half* __restrict__ W, float* __restrict__ B, __half* __restrict__ Wr)
{
    int idx = blockIdx.x * 256 + threadIdx.x;
    if (idx < NWQ) {
        int m  = idx / (DM*DM/4);
        int r  = idx - m * (DM*DM/4);
        int k  = r >> 8;
        int j4 = r & 255;
        const float* src = (m == 0) ? wq : (m == 1) ? wk : wv;
        float4 v = *(const float4*)(src + k*DM + j4*4);
        *(uint2*)(W + (size_t)k*DM3 + m*DM + j4*4) =
            make_uint2(packh2(v.x, v.y), packh2(v.z, v.w));
    } else if (idx < NWQ + NB4) {
        int i = idx - NWQ;
        int m = i >> 8, j4 = i & 255;
        const float* src = (m == 0) ? bq : (m == 1) ? bk : bv;
        *(float4*)(B + m*DM + j4*4) = *(const float4*)(src + j4*4);
    } else if (idx < PREP_TOTAL) {
        int i = idx - NWQ - NB4;
        const float* src;
        int local;
        if (i < NW4_WO)                   { src = wo; local = i; }
        else if (i < NW4_WO + NW4_W1)     { src = w1; local = i - NW4_WO; }
        else                              { src = w2; local = i - NW4_WO - NW4_W1; }
        float4 v = *(const float4*)(src + (size_t)local*4);
        *(uint2*)(Wr + (size_t)i*4) = make_uint2(packh2(v.x, v.y), packh2(v.z, v.w));
    }
}

// ---------------- LayerNorm: warp-per-row, shuffle-only -------------------
// 256 thr = 8 warps, 8 rows/block, 512 blocks. x kept in registers.
__global__ void __launch_bounds__(256) ln_kernel(
    const float* __restrict__ X, const float* __restrict__ gamma,
    const float* __restrict__ beta, __half* __restrict__ Y)
{
    const int w = threadIdx.x >> 5, lane = threadIdx.x & 31;
    const int row = blockIdx.x * 8 + w;
    const float* xr = X + (size_t)row * DM;

    float4 xv[8];
    float s = 0.f, s2 = 0.f;
    #pragma unroll
    for (int i = 0; i < 8; i++) {
        xv[i] = *(const float4*)(xr + i*128 + lane*4);
        s  += xv[i].x + xv[i].y + xv[i].z + xv[i].w;
        s2 += xv[i].x*xv[i].x + xv[i].y*xv[i].y
            + xv[i].z*xv[i].z + xv[i].w*xv[i].w;
    }
    #pragma unroll
    for (int o = 16; o; o >>= 1) {
        s  += __shfl_xor_sync(0xffffffffu, s,  o);
        s2 += __shfl_xor_sync(0xffffffffu, s2, o);
    }
    const float mean = s * (1.0f / DM);
    const float var  = (s2 - s * mean) * (1.0f / (DM - 1));   // unbiased (ddof=1)
    const float inv  = 1.0f / (sqrtf(var) + 1e-6f);           // eps OUTSIDE sqrt

    __half* yr = Y + (size_t)row * DM;
    #pragma unroll
    for (int i = 0; i < 8; i++) {
        float4 g4 = *(const float4*)(gamma + i*128 + lane*4);
        float4 b4 = *(const float4*)(beta  + i*128 + lane*4);
        *(uint2*)(yr + i*128 + lane*4) = make_uint2(
            packh2(g4.x * (xv[i].x - mean) * inv + b4.x,
                   g4.y * (xv[i].y - mean) * inv + b4.y),
            packh2(g4.z * (xv[i].z - mean) * inv + b4.z,
                   g4.w * (xv[i].w - mean) * inv + b4.w));
    }
}

// ---------------- fp16 GEMM 128x128, 6-stage ring (R13 verbatim) ----------
#define BK 32
#define AS 40
#define BS 136
#define A_HALVES (128*AS)
#define B_HALVES (BK*BS)
#define NSTG 6
#define GEMM_SMEM (NSTG*(A_HALVES + B_HALVES)*2)

template<int EPI>
__global__ void __launch_bounds__(128, 2) gemm_tc(
    const __half* __restrict__ A, const __half* __restrict__ Bm,
    const float* __restrict__ bias, const float* __restrict__ res,
    void* __restrict__ Cv, int M, int N, int K)
{
    extern __shared__ __half hsm[];
    __half* As = hsm;
    __half* Bs = hsm + NSTG*A_HALVES;

    const int tid  = threadIdx.x;
    const int lane = tid & 31, wid = tid >> 5;
    const int wm = wid >> 1, wn = wid & 1;
    const int gid = lane >> 2, tig = lane & 3;
    const int bm = blockIdx.y * 128, bn = blockIdx.x * 128;

    const int ar0 = tid >> 2, ac = (tid & 3) * 8;
    const int br0 = tid >> 4, bc = (tid & 15) * 8;
    const uint32_t as_u = s2u(As);
    const uint32_t bs_u = s2u(Bs);

    const int NT = K >> 5;

    auto prefetch = [&](int kt) {
        const int buf = kt % NSTG;
        const __half* Ag = A + (size_t)(bm + ar0) * K + kt*BK + ac;
        uint32_t ad = as_u + (uint32_t)(buf*A_HALVES + ar0*AS + ac) * 2;
        #pragma unroll
        for (int i = 0; i < 4; i++)
            cpasync16(ad + (uint32_t)(i*32*AS*2), Ag + (size_t)(i*32)*K);
        const __half* Bg = Bm + (size_t)(kt*BK + br0) * N + bn + bc;
        uint32_t bd = bs_u + (uint32_t)(buf*B_HALVES + br0*BS + bc) * 2;
        #pragma unroll
        for (int i = 0; i < 4; i++)
            cpasync16(bd + (uint32_t)(i*8*BS*2), Bg + (size_t)(i*8)*N);
    };

    const int a_row_l = (lane & 7) + (lane & 8);
    const int a_kcol  = ((lane >> 4) & 1) * 8;
    const uint32_t a_lane_off = (uint32_t)(((wm*64 + a_row_l) * AS + a_kcol) * 2);
    const int b_row_l = lane & 15;
    const int b_ncol  = ((lane >> 4) & 1) * 8;
    const uint32_t b_lane_off = (uint32_t)((b_row_l * BS + wn*64 + b_ncol) * 2);

    float acc[4][8][4];
    #pragma unroll
    for (int a = 0; a < 4; a++)
        #pragma unroll
        for (int b = 0; b < 8; b++)
            #pragma unroll
            for (int c = 0; c < 4; c++) acc[a][b][c] = 0.f;

    prefetch(0); CP_COMMIT();
    prefetch(1); CP_COMMIT();
    prefetch(2); CP_COMMIT();
    prefetch(3); CP_COMMIT();

    for (int kt = 0; kt < NT; kt += 2) {
        CP_WAIT2();
        __syncthreads();
        #pragma unroll
        for (int st = 0; st < 2; st++) {
            const int buf = (kt + st) % NSTG;
            const uint32_t abase = as_u + (uint32_t)(buf * A_HALVES * 2) + a_lane_off;
            const uint32_t bbase = bs_u + (uint32_t)(buf * B_HALVES * 2) + b_lane_off;
            #pragma unroll
            for (int ks = 0; ks < 2; ks++) {
                uint32_t af[4][4];
                #pragma unroll
                for (int mt = 0; mt < 4; mt++)
                    ldsm_x4(af[mt][0], af[mt][1], af[mt][2], af[mt][3],
                            abase + (uint32_t)(mt*16*AS*2 + ks*32));
                #pragma unroll
                for (int p = 0; p < 4; p++) {
                    uint32_t b0, b1, b2, b3;
                    ldsm_x4_t(b0, b1, b2, b3,
                              bbase + (uint32_t)(ks*16*BS*2 + p*32));
                    #pragma unroll
                    for (int mt = 0; mt < 4; mt++) {
                        mma16(acc[mt][2*p],   af[mt][0], af[mt][1], af[mt][2], af[mt][3], b0, b1);
                        mma16(acc[mt][2*p+1], af[mt][0], af[mt][1], af[mt][2], af[mt][3], b2, b3);
                    }
                }
            }
        }
        if (kt + 4 < NT) prefetch(kt + 4);
        CP_COMMIT();
        if (kt + 5 < NT) prefetch(kt + 5);
        CP_COMMIT();
    }

    #pragma unroll
    for (int mt = 0; mt < 4; mt++) {
        const int r0 = bm + wm*64 + mt*16 + gid;
        #pragma unroll
        for (int nt = 0; nt < 8; nt++) {
            const int cn = bn + wn*64 + nt*8 + tig*2;
            float bx = bias[cn], by = bias[cn+1];
            float2 v0 = make_float2(acc[mt][nt][0] + bx, acc[mt][nt][1] + by);
            float2 v1 = make_float2(acc[mt][nt][2] + bx, acc[mt][nt][3] + by);
            size_t o0 = (size_t)r0 * N + cn;
            size_t o1 = o0 + (size_t)8 * N;
            if (EPI == 0) {
                __half* C = (__half*)Cv;
                *(uint32_t*)(C + o0) = packh2(v0.x, v0.y);
                *(uint32_t*)(C + o1) = packh2(v1.x, v1.y);
            }
            if (EPI == 1) {
                __half* C = (__half*)Cv;
                *(uint32_t*)(C + o0) = packh2(fmaxf(v0.x, 0.f), fmaxf(v0.y, 0.f));
                *(uint32_t*)(C + o1) = packh2(fmaxf(v1.x, 0.f), fmaxf(v1.y, 0.f));
            }
            if (EPI == 2) {
                float* C = (float*)Cv;
                float2 r0v = *(const float2*)(res + o0);
                float2 r1v = *(const float2*)(res + o1);
                *(float2*)(C + o0) = make_float2(v0.x + r0v.x, v0.y + r0v.y);
                *(float2*)(C + o1) = make_float2(v1.x + r1v.x, v1.y + r1v.y);
            }
        }
    }
}

// ---------------- fp16 flash attention (Q pre-scaled by 1/8) --------------
#define QS 72
#define AQ_H (64*QS)
#define ATT_SMEM ((AQ_H + 2*AQ_H + 2*AQ_H) * 2 + 2*64*4)

__global__ void __launch_bounds__(128) attn_tc(
    const __half* __restrict__ QKV, const int* __restrict__ mask,
    __half* __restrict__ O)
{
    extern __shared__ __half hsm[];
    __half* q_s = hsm;
    __half* k_s = q_s + AQ_H;          // 2 stages
    __half* v_s = k_s + 2*AQ_H;        // 2 stages
    int*    m_s = (int*)(v_s + 2*AQ_H);// [2][64]

    const int tid = threadIdx.x, lane = tid & 31, w = tid >> 5;
    const int gid = lane >> 2, tig = lane & 3;
    const int qt = blockIdx.x, h = blockIdx.y, b = blockIdx.z;
    const __half* Qp = QKV + (size_t)b * SQ * DM3 + (size_t)h * DK;
    const __half* Kp = Qp + DM;
    const __half* Vp = Qp + 2*DM;
    const uint32_t qs_u = s2u(q_s);
    const uint32_t ks_u = s2u(k_s);
    const uint32_t vs_u = s2u(v_s);

    auto kv_prefetch = [&](int t, int buf) {
        #pragma unroll
        for (int i = 0; i < 4; i++) {
            int c = tid + i*128;
            int r = c >> 3, c8 = c & 7;
            size_t goff = (size_t)(t*64 + r) * DM3 + c8*8;
            uint32_t soff = (uint32_t)((buf*AQ_H + r*QS + c8*8) * 2);
            cpasync16(ks_u + soff, Kp + goff);
            cpasync16(vs_u + soff, Vp + goff);
        }
    };

    kv_prefetch(0, 0); CP_COMMIT();

    // Q tile, pre-scaled by 0.125 (exact power of 2 in fp16)
    const __half2 qscale = __float2half2_rn(0.125f);
    for (int i = tid; i < 64*8; i += 128) {
        int r = i >> 3, c8 = i & 7;
        uint4 qv = *(const uint4*)(Qp + (size_t)(qt*64 + r) * DM3 + c8*8);
        __half2* qh = (__half2*)&qv;
        qh[0] = __hmul2(qh[0], qscale);
        qh[1] = __hmul2(qh[1], qscale);
        qh[2] = __hmul2(qh[2], qscale);
        qh[3] = __hmul2(qh[3], qscale);
        *(uint4*)&q_s[r*QS + c8*8] = qv;
    }

    const int a_row_l = (lane & 7) + (lane & 8);
    const int a_kcol  = ((lane >> 4) & 1) * 8;
    const uint32_t q_lane = (uint32_t)(((w*16 + a_row_l) * QS + a_kcol) * 2);
    const int b_row_l = lane & 15;
    const int b_col_l = ((lane >> 4) & 1) * 8;

    float o[8][4];
    #pragma unroll
    for (int nt = 0; nt < 8; nt++)
        #pragma unroll
        for (int i = 0; i < 4; i++) o[nt][i] = 0.f;
    float l0 = 0.f, l1 = 0.f;
    const int NTI = SQ/64;

    for (int t = 0; t < NTI; t++) {
        if (t + 1 < NTI) kv_prefetch(t + 1, (t + 1) & 1);
        CP_COMMIT();
        if (tid < 64) m_s[(t & 1)*64 + tid] = mask[b*SQ + t*64 + tid];
        CP_WAIT1();
        __syncthreads();
        const uint32_t kbase = ks_u + (uint32_t)((t & 1) * AQ_H * 2);
        const uint32_t vbase = vs_u + (uint32_t)((t & 1) * AQ_H * 2);
        const int* mb = m_s + (t & 1) * 64;

        float s[8][4];
        #pragma unroll
        for (int nt = 0; nt < 8; nt++)
            #pragma unroll
            for (int i = 0; i < 4; i++) s[nt][i] = 0.f;
        #pragma unroll
        for (int ks = 0; ks < 4; ks++) {
            uint32_t a0, a1, a2, a3;
            ldsm_x4(a0, a1, a2, a3, qs_u + q_lane + (uint32_t)(ks*32));
            #pragma unroll
            for (int p = 0; p < 4; p++) {
                uint32_t r0, r1, r2, r3;
                ldsm_x4(r0, r1, r2, r3,
                    kbase + (uint32_t)(((p*16 + b_row_l)*QS + ks*16 + b_col_l) * 2));
                mma16(s[2*p],   a0, a1, a2, a3, r0, r2);
                mma16(s[2*p+1], a0, a1, a2, a3, r1, r3);
            }
        }

        uint32_t ph[8][2];
        #pragma unroll
        for (int nt = 0; nt < 8; nt++) {
            const int c0 = nt*8 + tig*2;
            const bool z0 = (mb[c0] == 0), z1 = (mb[c0+1] == 0);
            float p0 = __expf(z0 ? -1e9f : s[nt][0]);
            float p1 = __expf(z1 ? -1e9f : s[nt][1]);
            float p2 = __expf(z0 ? -1e9f : s[nt][2]);
            float p3 = __expf(z1 ? -1e9f : s[nt][3]);
            l0 += p0 + p1;  l1 += p2 + p3;
            ph[nt][0] = packh2(p0, p1);
            ph[nt][1] = packh2(p2, p3);
        }

        #pragma unroll
        for (int ks = 0; ks < 4; ks++) {
            uint32_t pa0 = ph[2*ks][0],   pa1 = ph[2*ks][1];
            uint32_t pa2 = ph[2*ks+1][0], pa3 = ph[2*ks+1][1];
            #pragma unroll
            for (int p = 0; p < 4; p++) {
                uint32_t r0, r1, r2, r3;
                ldsm_x4_t(r0, r1, r2, r3,
                    vbase + (uint32_t)(((ks*16 + b_row_l)*QS + p*16 + b_col_l) * 2));
                mma16(o[2*p],   pa0, pa1, pa2, pa3, r0, r1);
                mma16(o[2*p+1], pa0, pa1, pa2, pa3, r2, r3);
            }
        }
        __syncthreads();
    }

    l0 += __shfl_xor_sync(0xffffffffu, l0, 1);
    l0 += __shfl_xor_sync(0xffffffffu, l0, 2);
    l1 += __shfl_xor_sync(0xffffffffu, l1, 1);
    l1 += __shfl_xor_sync(0xffffffffu, l1, 2);
    const float n0 = 1.0f / l0, n1 = 1.0f / l1;
    #pragma unroll
    for (int nt = 0; nt < 8; nt++) {
        const int cn = h*DK + nt*8 + tig*2;
        size_t r0 = (size_t)(b*SQ + qt*64 + w*16 + gid) * DM + cn;
        size_t r1 = r0 + (size_t)8 * DM;
        *(uint32_t*)(O + r0) = packh2(o[nt][0]*n0, o[nt][1]*n0);
        *(uint32_t*)(O + r1) = packh2(o[nt][2]*n1, o[nt][3]*n1);
    }
}

// --------------------------------------------------------------------------
extern "C" void kernel_launch(void* const* d_in, const int* in_sizes, int n_in,
                              void* d_out, int out_size)
{
    const float* x    = (const float*)d_in[0];
    const int*   mask = (const int*)  d_in[1];
    const float* wq = (const float*)d_in[2],  *bq = (const float*)d_in[3];
    const float* wk = (const float*)d_in[4],  *bk = (const float*)d_in[5];
    const float* wv = (const float*)d_in[6],  *bv = (const float*)d_in[7];
    const float* wo = (const float*)d_in[8],  *bo = (const float*)d_in[9];
    const float* w1 = (const float*)d_in[10], *b1 = (const float*)d_in[11];
    const float* w2 = (const float*)d_in[12], *b2 = (const float*)d_in[13];
    const float* g1 = (const float*)d_in[14], *be1 = (const float*)d_in[15];
    const float* g2 = (const float*)d_in[16], *be2 = (const float*)d_in[17];
    float* out = (float*)d_out;

    __half *xn, *qkvh, *ctxh, *hbuf, *Wqh, *Wrh;
    float *x1, *Bq;
    cudaGetSymbolAddress((void**)&xn,   g_xn_h);
    cudaGetSymbolAddress((void**)&qkvh, g_qkv_h);
    cudaGetSymbolAddress((void**)&ctxh, g_ctx_h);
    cudaGetSymbolAddress((void**)&x1,   g_x1);
    cudaGetSymbolAddress((void**)&hbuf, g_h_h);
    cudaGetSymbolAddress((void**)&Wqh,  g_wqkvh);
    cudaGetSymbolAddress((void**)&Bq,   g_bqkv);
    cudaGetSymbolAddress((void**)&Wrh,  g_wrh);
    __half* wo_h = Wrh;
    __half* w1_h = Wrh + DM*DM;
    __half* w2_h = Wrh + DM*DM + DM*DFF;

    cudaFuncSetAttribute(gemm_tc<0>, cudaFuncAttributeMaxDynamicSharedMemorySize, GEMM_SMEM);
    cudaFuncSetAttribute(gemm_tc<1>, cudaFuncAttributeMaxDynamicSharedMemorySize, GEMM_SMEM);
    cudaFuncSetAttribute(gemm_tc<2>, cudaFuncAttributeMaxDynamicSharedMemorySize, GEMM_SMEM);
    cudaFuncSetAttribute(attn_tc,    cudaFuncAttributeMaxDynamicSharedMemorySize, ATT_SMEM);

    dim3 gQKV(DM3/128, ROWS/128);    // 24 x 32
    dim3 gProj(DM/128,  ROWS/128);   // 8 x 32
    dim3 gFF1 (DFF/128, ROWS/128);   // 32 x 32

    // 0) fused weight prep (single launch)
    prep_all<<<(PREP_TOTAL + 255)/256, 256>>>(
        wq, wk, wv, bq, bk, bv, wo, w1, w2, Wqh, Bq, Wrh);
    // 1) LN1 -> half (warp-per-row)
    ln_kernel<<<ROWS/8, 256>>>(x, g1, be1, xn);
    // 2) fused QKV projection (fp16 mma, half out)
    gemm_tc<0><<<gQKV, 128, GEMM_SMEM>>>(xn, Wqh, Bq, nullptr, qkvh, ROWS, DM3, DM);
    // 3) fused masked flash attention (fp16) -> ctx half
    attn_tc<<<dim3(SQ/64, NH, BATCH), 128, ATT_SMEM>>>(qkvh, mask, ctxh);
    // 4) out-proj + residual(x) -> x1 (f32)
    gemm_tc<2><<<gProj, 128, GEMM_SMEM>>>(ctxh, wo_h, bo, x, x1, ROWS, DM, DM);
    // 5) LN2 -> half
    ln_kernel<<<ROWS/8, 256>>>(x1, g2, be2, xn);
    // 6) FFN up + relu -> half
    gemm_tc<1><<<gFF1, 128, GEMM_SMEM>>>(xn, w1_h, b1, nullptr, hbuf, ROWS, DFF, DM);
    // 7) FFN down + residual(x1) -> out (f32)
    gemm_tc<2><<<gProj, 128, GEMM_SMEM>>>(hbuf, w2_h, b2, x1, out, ROWS, DM, DFF);
}

// round 16
// speedup vs baseline: 1.1011x; 1.0091x over previous
#include <cuda_runtime.h>
#include <cuda_fp16.h>
#include <math.h>
#include <stdint.h>

#define DM    1024
#define DFF   4096
#define SQ    2048
#define BATCH 2
#define ROWS  (BATCH*SQ)   /* 4096 */
#define DK    64
#define NH    16
#define DM3   (3*DM)

// Q pre-scale: (1/sqrt(64)) * log2(e), folded in fp32 before half rounding
#define QSC 0.18033688011112042f

// ---------------- scratch (device globals; no allocation) ----------------
__device__ __half g_xn_h [ROWS*DM];
__device__ __half g_qkv_h[ROWS*DM3];
__device__ __half g_ctx_h[ROWS*DM];
__device__ float  g_x1   [ROWS*DM];
__device__ __half g_h_h  [ROWS*DFF];
__device__ __half g_wqkvh[DM*DM3];
__device__ float  g_bqkv [DM3];
__device__ __half g_wrh  [DM*DM + DM*DFF + DFF*DM];   // half wo|w1|w2

// ---------------- helpers -------------------------------------------------
__device__ __forceinline__ void mma16(float* c,
    uint32_t a0, uint32_t a1, uint32_t a2, uint32_t a3,
    uint32_t b0, uint32_t b1)
{
    asm volatile(
      "mma.sync.aligned.m16n8k16.row.col.f32.f16.f16.f32 "
      "{%0,%1,%2,%3},{%4,%5,%6,%7},{%8,%9},{%0,%1,%2,%3};"
      : "+f"(c[0]), "+f"(c[1]), "+f"(c[2]), "+f"(c[3])
      : "r"(a0), "r"(a1), "r"(a2), "r"(a3), "r"(b0), "r"(b1));
}
__device__ __forceinline__ void ldsm_x4(uint32_t& r0, uint32_t& r1,
                                        uint32_t& r2, uint32_t& r3, uint32_t addr)
{
    asm volatile("ldmatrix.sync.aligned.m8n8.x4.shared.b16 {%0,%1,%2,%3}, [%4];"
                 : "=r"(r0), "=r"(r1), "=r"(r2), "=r"(r3) : "r"(addr));
}
__device__ __forceinline__ void ldsm_x4_t(uint32_t& r0, uint32_t& r1,
                                          uint32_t& r2, uint32_t& r3, uint32_t addr)
{
    asm volatile("ldmatrix.sync.aligned.m8n8.x4.trans.shared.b16 {%0,%1,%2,%3}, [%4];"
                 : "=r"(r0), "=r"(r1), "=r"(r2), "=r"(r3) : "r"(addr));
}
__device__ __forceinline__ void ldsm_x2_t(uint32_t& r0, uint32_t& r1, uint32_t addr)
{
    asm volatile("ldmatrix.sync.aligned.m8n8.x2.trans.shared.b16 {%0,%1}, [%2];"
                 : "=r"(r0), "=r"(r1) : "r"(addr));
}
__device__ __forceinline__ float ex2f(float x) {
    float y; asm("ex2.approx.f32 %0, %1;" : "=f"(y) : "f"(x)); return y;
}
__device__ __forceinline__ uint32_t s2u(const void* p) {
    uint32_t a;
    asm("{.reg .u64 t; cvta.to.shared.u64 t, %1; cvt.u32.u64 %0, t;}"
        : "=r"(a) : "l"(p));
    return a;
}
__device__ __forceinline__ void cpasync16(uint32_t dst, const void* src) {
    asm volatile("cp.async.cg.shared.global [%0], [%1], 16;" :: "r"(dst), "l"(src));
}
__device__ __forceinline__ uint32_t packh2(float a, float b) {
    __half2 h = __floats2half2_rn(a, b);
    return *(uint32_t*)&h;
}
#define CP_COMMIT() asm volatile("cp.async.commit_group;")
#define CP_WAIT2()  asm volatile("cp.async.wait_group 2;")
#define CP_WAIT1()  asm volatile("cp.async.wait_group 1;")

// ---------------- fused weight prep: qkv pack + biases + wo|w1|w2 ---------
#define NWQ   (3*(DM*DM/4))
#define NB4   (3*256)
#define NW4_WO (DM*DM/4)
#define NW4_W1 (DM*DFF/4)
#define NW4_W2 (DFF*DM/4)
#define NW4_R  (NW4_WO + NW4_W1 + NW4_W2)
#define PREP_TOTAL (NWQ + NB4 + NW4_R)

__global__ void __launch_bounds__(256) prep_all(
    const float* __restrict__ wq, const float* __restrict__ wk,
    const float* __restrict__ wv, const float* __restrict__ bq,
    const float* __restrict__ bk, const float* __restrict__ bv,
    const float* __restrict__ wo, const float* __restrict__ w1,
    const float* __restrict__ w2,
    __half* __restrict__ W, float* __restrict__ B, __half* __restrict__ Wr)
{
    int idx = blockIdx.x * 256 + threadIdx.x;
    if (idx < NWQ) {
        int m  = idx / (DM*DM/4);
        int r  = idx - m * (DM*DM/4);
        int k  = r >> 8;
        int j4 = r & 255;
        const float* src = (m == 0) ? wq : (m == 1) ? wk : wv;
        float4 v = *(const float4*)(src + k*DM + j4*4);
        *(uint2*)(W + (size_t)k*DM3 + m*DM + j4*4) =
            make_uint2(packh2(v.x, v.y), packh2(v.z, v.w));
    } else if (idx < NWQ + NB4) {
        int i = idx - NWQ;
        int m = i >> 8, j4 = i & 255;
        const float* src = (m == 0) ? bq : (m == 1) ? bk : bv;
        *(float4*)(B + m*DM + j4*4) = *(const float4*)(src + j4*4);
    } else if (idx < PREP_TOTAL) {
        int i = idx - NWQ - NB4;
        const float* src;
        int local;
        if (i < NW4_WO)                   { src = wo; local = i; }
        else if (i < NW4_WO + NW4_W1)     { src = w1; local = i - NW4_WO; }
        else                              { src = w2; local = i - NW4_WO - NW4_W1; }
        float4 v = *(const float4*)(src + (size_t)local*4);
        *(uint2*)(Wr + (size_t)i*4) = make_uint2(packh2(v.x, v.y), packh2(v.z, v.w));
    }
}

// ---------------- LayerNorm: warp-per-row, shuffle-only -------------------
__global__ void __launch_bounds__(256) ln_kernel(
    const float* __restrict__ X, const float* __restrict__ gamma,
    const float* __restrict__ beta, __half* __restrict__ Y)
{
    const int w = threadIdx.x >> 5, lane = threadIdx.x & 31;
    const int row = blockIdx.x * 8 + w;
    const float* xr = X + (size_t)row * DM;

    float4 xv[8];
    float s = 0.f, s2 = 0.f;
    #pragma unroll
    for (int i = 0; i < 8; i++) {
        xv[i] = *(const float4*)(xr + i*128 + lane*4);
        s  += xv[i].x + xv[i].y + xv[i].z + xv[i].w;
        s2 += xv[i].x*xv[i].x + xv[i].y*xv[i].y
            + xv[i].z*xv[i].z + xv[i].w*xv[i].w;
    }
    #pragma unroll
    for (int o = 16; o; o >>= 1) {
        s  += __shfl_xor_sync(0xffffffffu, s,  o);
        s2 += __shfl_xor_sync(0xffffffffu, s2, o);
    }
    const float mean = s * (1.0f / DM);
    const float var  = (s2 - s * mean) * (1.0f / (DM - 1));   // unbiased (ddof=1)
    const float inv  = 1.0f / (sqrtf(var) + 1e-6f);           // eps OUTSIDE sqrt

    __half* yr = Y + (size_t)row * DM;
    #pragma unroll
    for (int i = 0; i < 8; i++) {
        float4 g4 = *(const float4*)(gamma + i*128 + lane*4);
        float4 b4 = *(const float4*)(beta  + i*128 + lane*4);
        *(uint2*)(yr + i*128 + lane*4) = make_uint2(
            packh2(g4.x * (xv[i].x - mean) * inv + b4.x,
                   g4.y * (xv[i].y - mean) * inv + b4.y),
            packh2(g4.z * (xv[i].z - mean) * inv + b4.z,
                   g4.w * (xv[i].w - mean) * inv + b4.w));
    }
}

// ---------------- fp16 GEMM 128x128, 6-stage ring (R13 core) --------------
// EPI: 0=half out, Q cols (<DM) pre-scaled by QSC (qkv); 1=relu half out;
//      2=+residual f32 out
#define BK 32
#define AS 40
#define BS 136
#define A_HALVES (128*AS)
#define B_HALVES (BK*BS)
#define NSTG 6
#define GEMM_SMEM (NSTG*(A_HALVES + B_HALVES)*2)

template<int EPI>
__global__ void __launch_bounds__(128, 2) gemm_tc(
    const __half* __restrict__ A, const __half* __restrict__ Bm,
    const float* __restrict__ bias, const float* __restrict__ res,
    void* __restrict__ Cv, int M, int N, int K)
{
    extern __shared__ __half hsm[];
    __half* As = hsm;
    __half* Bs = hsm + NSTG*A_HALVES;

    const int tid  = threadIdx.x;
    const int lane = tid & 31, wid = tid >> 5;
    const int wm = wid >> 1, wn = wid & 1;
    const int gid = lane >> 2, tig = lane & 3;
    const int bm = blockIdx.y * 128, bn = blockIdx.x * 128;

    const int ar0 = tid >> 2, ac = (tid & 3) * 8;
    const int br0 = tid >> 4, bc = (tid & 15) * 8;
    const uint32_t as_u = s2u(As);
    const uint32_t bs_u = s2u(Bs);

    const int NT = K >> 5;

    auto prefetch = [&](int kt) {
        const int buf = kt % NSTG;
        const __half* Ag = A + (size_t)(bm + ar0) * K + kt*BK + ac;
        uint32_t ad = as_u + (uint32_t)(buf*A_HALVES + ar0*AS + ac) * 2;
        #pragma unroll
        for (int i = 0; i < 4; i++)
            cpasync16(ad + (uint32_t)(i*32*AS*2), Ag + (size_t)(i*32)*K);
        const __half* Bg = Bm + (size_t)(kt*BK + br0) * N + bn + bc;
        uint32_t bd = bs_u + (uint32_t)(buf*B_HALVES + br0*BS + bc) * 2;
        #pragma unroll
        for (int i = 0; i < 4; i++)
            cpasync16(bd + (uint32_t)(i*8*BS*2), Bg + (size_t)(i*8)*N);
    };

    const int a_row_l = (lane & 7) + (lane & 8);
    const int a_kcol  = ((lane >> 4) & 1) * 8;
    const uint32_t a_lane_off = (uint32_t)(((wm*64 + a_row_l) * AS + a_kcol) * 2);
    const int b_row_l = lane & 15;
    const int b_ncol  = ((lane >> 4) & 1) * 8;
    const uint32_t b_lane_off = (uint32_t)((b_row_l * BS + wn*64 + b_ncol) * 2);

    float acc[4][8][4];
    #pragma unroll
    for (int a = 0; a < 4; a++)
        #pragma unroll
        for (int b = 0; b < 8; b++)
            #pragma unroll
            for (int c = 0; c < 4; c++) acc[a][b][c] = 0.f;

    prefetch(0); CP_COMMIT();
    prefetch(1); CP_COMMIT();
    prefetch(2); CP_COMMIT();
    prefetch(3); CP_COMMIT();

    for (int kt = 0; kt < NT; kt += 2) {
        CP_WAIT2();
        __syncthreads();
        #pragma unroll
        for (int st = 0; st < 2; st++) {
            const int buf = (kt + st) % NSTG;
            const uint32_t abase = as_u + (uint32_t)(buf * A_HALVES * 2) + a_lane_off;
            const uint32_t bbase = bs_u + (uint32_t)(buf * B_HALVES * 2) + b_lane_off;
            #pragma unroll
            for (int ks = 0; ks < 2; ks++) {
                uint32_t af[4][4];
                #pragma unroll
                for (int mt = 0; mt < 4; mt++)
                    ldsm_x4(af[mt][0], af[mt][1], af[mt][2], af[mt][3],
                            abase + (uint32_t)(mt*16*AS*2 + ks*32));
                #pragma unroll
                for (int p = 0; p < 4; p++) {
                    uint32_t b0, b1, b2, b3;
                    ldsm_x4_t(b0, b1, b2, b3,
                              bbase + (uint32_t)(ks*16*BS*2 + p*32));
                    #pragma unroll
                    for (int mt = 0; mt < 4; mt++) {
                        mma16(acc[mt][2*p],   af[mt][0], af[mt][1], af[mt][2], af[mt][3], b0, b1);
                        mma16(acc[mt][2*p+1], af[mt][0], af[mt][1], af[mt][2], af[mt][3], b2, b3);
                    }
                }
            }
        }
        if (kt + 4 < NT) prefetch(kt + 4);
        CP_COMMIT();
        if (kt + 5 < NT) prefetch(kt + 5);
        CP_COMMIT();
    }

    #pragma unroll
    for (int mt = 0; mt < 4; mt++) {
        const int r0 = bm + wm*64 + mt*16 + gid;
        #pragma unroll
        for (int nt = 0; nt < 8; nt++) {
            const int cn = bn + wn*64 + nt*8 + tig*2;
            float bx = bias[cn], by = bias[cn+1];
            float2 v0 = make_float2(acc[mt][nt][0] + bx, acc[mt][nt][1] + by);
            float2 v1 = make_float2(acc[mt][nt][2] + bx, acc[mt][nt][3] + by);
            size_t o0 = (size_t)r0 * N + cn;
            size_t o1 = o0 + (size_t)8 * N;
            if (EPI == 0) {
                const float sc = (cn < DM) ? QSC : 1.0f;   // pre-scale Q cols
                __half* C = (__half*)Cv;
                *(uint32_t*)(C + o0) = packh2(v0.x*sc, v0.y*sc);
                *(uint32_t*)(C + o1) = packh2(v1.x*sc, v1.y*sc);
            }
            if (EPI == 1) {
                __half* C = (__half*)Cv;
                *(uint32_t*)(C + o0) = packh2(fmaxf(v0.x, 0.f), fmaxf(v0.y, 0.f));
                *(uint32_t*)(C + o1) = packh2(fmaxf(v1.x, 0.f), fmaxf(v1.y, 0.f));
            }
            if (EPI == 2) {
                float* C = (float*)Cv;
                float2 r0v = *(const float2*)(res + o0);
                float2 r1v = *(const float2*)(res + o1);
                *(float2*)(C + o0) = make_float2(v0.x + r0v.x, v0.y + r0v.y);
                *(float2*)(C + o1) = make_float2(v1.x + r1v.x, v1.y + r1v.y);
            }
        }
    }
}

// ---------------- fp16 flash attention: mask-in-V, l-via-mma --------------
// Q pre-scaled by QSC upstream. Masked keys: V row zeroed + mask col 64.
// l computed by an extra n-tile mma against V cols 64-71 (col64 = mask).
#define QS 72
#define AQ_H (64*QS)
#define ATT_SMEM ((AQ_H + 2*AQ_H + 2*AQ_H) * 2)

__global__ void __launch_bounds__(128) attn_tc(
    const __half* __restrict__ QKV, const int* __restrict__ mask,
    __half* __restrict__ O)
{
    extern __shared__ __half hsm[];
    __half* q_s = hsm;
    __half* k_s = q_s + AQ_H;          // 2 stages
    __half* v_s = k_s + 2*AQ_H;        // 2 stages

    const int tid = threadIdx.x, lane = tid & 31, w = tid >> 5;
    const int gid = lane >> 2, tig = lane & 3;
    const int qt = blockIdx.x, h = blockIdx.y, b = blockIdx.z;
    const __half* Qp = QKV + (size_t)b * SQ * DM3 + (size_t)h * DK;
    const __half* Kp = Qp + DM;
    const __half* Vp = Qp + 2*DM;
    const uint32_t qs_u = s2u(q_s);
    const uint32_t ks_u = s2u(k_s);
    const uint32_t vs_u = s2u(v_s);

    auto kv_prefetch = [&](int t, int buf) {
        #pragma unroll
        for (int i = 0; i < 4; i++) {
            int c = tid + i*128;
            int r = c >> 3, c8 = c & 7;
            size_t goff = (size_t)(t*64 + r) * DM3 + c8*8;
            uint32_t soff = (uint32_t)((buf*AQ_H + r*QS + c8*8) * 2);
            cpasync16(ks_u + soff, Kp + goff);
            cpasync16(vs_u + soff, Vp + goff);
        }
    };

    kv_prefetch(0, 0); CP_COMMIT();

    // zero V pad cols 64-71 for both stages (col64 rewritten per tile)
    {
        int st = tid >> 6, r = tid & 63;
        *(uint4*)(v_s + st*AQ_H + r*QS + 64) = make_uint4(0,0,0,0);
    }

    // Q tile (already scaled by QSC upstream)
    for (int i = tid; i < 64*8; i += 128) {
        int r = i >> 3, c8 = i & 7;
        *(uint4*)&q_s[r*QS + c8*8] =
            *(const uint4*)(Qp + (size_t)(qt*64 + r) * DM3 + c8*8);
    }

    const int a_row_l = (lane & 7) + (lane & 8);
    const int a_kcol  = ((lane >> 4) & 1) * 8;
    const uint32_t q_lane = (uint32_t)(((w*16 + a_row_l) * QS + a_kcol) * 2);
    const int b_row_l = lane & 15;
    const int b_col_l = ((lane >> 4) & 1) * 8;

    float o[8][4];
    #pragma unroll
    for (int nt = 0; nt < 8; nt++)
        #pragma unroll
        for (int i = 0; i < 4; i++) o[nt][i] = 0.f;
    float fl[4] = {0.f, 0.f, 0.f, 0.f};   // l accumulator (cols 64-71 tile)
    const int NTI = SQ/64;
    const __half h_one  = __float2half(1.0f);
    const __half h_zero = __float2half(0.0f);

    for (int t = 0; t < NTI; t++) {
        if (t + 1 < NTI) kv_prefetch(t + 1, (t + 1) & 1);
        CP_COMMIT();
        int mk = 0;
        if (tid < 64) mk = mask[b*SQ + t*64 + tid];
        CP_WAIT1();
        // V fixup: mask col + zero masked rows (before the barrier)
        if (tid < 64) {
            __half* vrow = v_s + (t & 1)*AQ_H + tid*QS;
            vrow[64] = mk ? h_one : h_zero;
            if (!mk) {
                uint4 z = make_uint4(0,0,0,0);
                #pragma unroll
                for (int i = 0; i < 8; i++) *(uint4*)(vrow + i*8) = z;
            }
        }
        __syncthreads();
        const uint32_t kbase = ks_u + (uint32_t)((t & 1) * AQ_H * 2);
        const uint32_t vbase = vs_u + (uint32_t)((t & 1) * AQ_H * 2);

        // --- S' = Qs @ K^T  (S' = S * log2e / sqrt(dk)) ---
        float s[8][4];
        #pragma unroll
        for (int nt = 0; nt < 8; nt++)
            #pragma unroll
            for (int i = 0; i < 4; i++) s[nt][i] = 0.f;
        #pragma unroll
        for (int ks = 0; ks < 4; ks++) {
            uint32_t a0, a1, a2, a3;
            ldsm_x4(a0, a1, a2, a3, qs_u + q_lane + (uint32_t)(ks*32));
            #pragma unroll
            for (int p = 0; p < 4; p++) {
                uint32_t r0, r1, r2, r3;
                ldsm_x4(r0, r1, r2, r3,
                    kbase + (uint32_t)(((p*16 + b_row_l)*QS + ks*16 + b_col_l) * 2));
                mma16(s[2*p],   a0, a1, a2, a3, r0, r2);
                mma16(s[2*p+1], a0, a1, a2, a3, r1, r3);
            }
        }

        // --- p = 2^(s')  (mask handled by V) -> half2 frags ---
        uint32_t ph[8][2];
        #pragma unroll
        for (int nt = 0; nt < 8; nt++) {
            ph[nt][0] = packh2(ex2f(s[nt][0]), ex2f(s[nt][1]));
            ph[nt][1] = packh2(ex2f(s[nt][2]), ex2f(s[nt][3]));
        }

        // --- O += P @ V ; fl += P @ maskcol ---
        #pragma unroll
        for (int ks = 0; ks < 4; ks++) {
            uint32_t pa0 = ph[2*ks][0],   pa1 = ph[2*ks][1];
            uint32_t pa2 = ph[2*ks+1][0], pa3 = ph[2*ks+1][1];
            #pragma unroll
            for (int p = 0; p < 4; p++) {
                uint32_t r0, r1, r2, r3;
                ldsm_x4_t(r0, r1, r2, r3,
                    vbase + (uint32_t)(((ks*16 + b_row_l)*QS + p*16 + b_col_l) * 2));
                mma16(o[2*p],   pa0, pa1, pa2, pa3, r0, r1);
                mma16(o[2*p+1], pa0, pa1, pa2, pa3, r2, r3);
            }
            uint32_t l0r, l1r;
            ldsm_x2_t(l0r, l1r,
                vbase + (uint32_t)(((ks*16 + b_row_l)*QS + 64) * 2));
            mma16(fl, pa0, pa1, pa2, pa3, l0r, l1r);
        }
        __syncthreads();
    }

    // broadcast l from tig==0 lanes (col 64 of the extra tile)
    const float l0 = __shfl_sync(0xffffffffu, fl[0], lane & 28);
    const float l1 = __shfl_sync(0xffffffffu, fl[2], lane & 28);
    const float n0 = 1.0f / l0, n1 = 1.0f / l1;
    #pragma unroll
    for (int nt = 0; nt < 8; nt++) {
        const int cn = h*DK + nt*8 + tig*2;
        size_t r0 = (size_t)(b*SQ + qt*64 + w*16 + gid) * DM + cn;
        size_t r1 = r0 + (size_t)8 * DM;
        *(uint32_t*)(O + r0) = packh2(o[nt][0]*n0, o[nt][1]*n0);
        *(uint32_t*)(O + r1) = packh2(o[nt][2]*n1, o[nt][3]*n1);
    }
}

// --------------------------------------------------------------------------
extern "C" void kernel_launch(void* const* d_in, const int* in_sizes, int n_in,
                              void* d_out, int out_size)
{
    const float* x    = (const float*)d_in[0];
    const int*   mask = (const int*)  d_in[1];
    const float* wq = (const float*)d_in[2],  *bq = (const float*)d_in[3];
    const float* wk = (const float*)d_in[4],  *bk = (const float*)d_in[5];
    const float* wv = (const float*)d_in[6],  *bv = (const float*)d_in[7];
    const float* wo = (const float*)d_in[8],  *bo = (const float*)d_in[9];
    const float* w1 = (const float*)d_in[10], *b1 = (const float*)d_in[11];
    const float* w2 = (const float*)d_in[12], *b2 = (const float*)d_in[13];
    const float* g1 = (const float*)d_in[14], *be1 = (const float*)d_in[15];
    const float* g2 = (const float*)d_in[16], *be2 = (const float*)d_in[17];
    float* out = (float*)d_out;

    __half *xn, *qkvh, *ctxh, *hbuf, *Wqh, *Wrh;
    float *x1, *Bq;
    cudaGetSymbolAddress((void**)&xn,   g_xn_h);
    cudaGetSymbolAddress((void**)&qkvh, g_qkv_h);
    cudaGetSymbolAddress((void**)&ctxh, g_ctx_h);
    cudaGetSymbolAddress((void**)&x1,   g_x1);
    cudaGetSymbolAddress((void**)&hbuf, g_h_h);
    cudaGetSymbolAddress((void**)&Wqh,  g_wqkvh);
    cudaGetSymbolAddress((void**)&Bq,   g_bqkv);
    cudaGetSymbolAddress((void**)&Wrh,  g_wrh);
    __half* wo_h = Wrh;
    __half* w1_h = Wrh + DM*DM;
    __half* w2_h = Wrh + DM*DM + DM*DFF;

    cudaFuncSetAttribute(gemm_tc<0>, cudaFuncAttributeMaxDynamicSharedMemorySize, GEMM_SMEM);
    cudaFuncSetAttribute(gemm_tc<1>, cudaFuncAttributeMaxDynamicSharedMemorySize, GEMM_SMEM);
    cudaFuncSetAttribute(gemm_tc<2>, cudaFuncAttributeMaxDynamicSharedMemorySize, GEMM_SMEM);
    cudaFuncSetAttribute(attn_tc,    cudaFuncAttributeMaxDynamicSharedMemorySize, ATT_SMEM);

    dim3 gQKV(DM3/128, ROWS/128);    // 24 x 32
    dim3 gProj(DM/128,  ROWS/128);   // 8 x 32
    dim3 gFF1 (DFF/128, ROWS/128);   // 32 x 32

    // 0) fused weight prep (single launch)
    prep_all<<<(PREP_TOTAL + 255)/256, 256>>>(
        wq, wk, wv, bq, bk, bv, wo, w1, w2, Wqh, Bq, Wrh);
    // 1) LN1 -> half (warp-per-row)
    ln_kernel<<<ROWS/8, 256>>>(x, g1, be1, xn);
    // 2) fused QKV projection (fp16 mma, half out; Q cols pre-scaled)
    gemm_tc<0><<<gQKV, 128, GEMM_SMEM>>>(xn, Wqh, Bq, nullptr, qkvh, ROWS, DM3, DM);
    // 3) fused masked flash attention (fp16, mask-in-V) -> ctx half
    attn_tc<<<dim3(SQ/64, NH, BATCH), 128, ATT_SMEM>>>(qkvh, mask, ctxh);
    // 4) out-proj + residual(x) -> x1 (f32)
    gemm_tc<2><<<gProj, 128, GEMM_SMEM>>>(ctxh, wo_h, bo, x, x1, ROWS, DM, DM);
    // 5) LN2 -> half
    ln_kernel<<<ROWS/8, 256>>>(x1, g2, be2, xn);
    // 6) FFN up + relu -> half
    gemm_tc<1><<<gFF1, 128, GEMM_SMEM>>>(xn, w1_h, b1, nullptr, hbuf, ROWS, DFF, DM);
    // 7) FFN down + residual(x1) -> out (f32)
    gemm_tc<2><<<gProj, 128, GEMM_SMEM>>>(hbuf, w2_h, b2, x1, out, ROWS, DM, DFF);
}